// round 15
// baseline (speedup 1.0000x reference)
#include <cuda_runtime.h>
#include <cuda_bf16.h>
#include <cstdint>

// ---------------- problem constants ----------------
#define BB 32
#define DD 768
#define DEPTH 12
#define HEADS 12
#define GRID_ 10
#define NCLS 40
#define TT 101
#define SEG 3200
#define TOTPTS 65536
#define MLPH 3072
#define BT 3232
#define EPSLN 1e-5f

typedef __nv_bfloat16 bf16;

// ---------------- scratch (device globals) ----------------
__device__ float g_cnt[SEG];
__device__ float g_csum[SEG * 3];
__device__ int   g_cell[TOTPTS];
__device__ float g_pooled[SEG * 128];
__device__ float g_pillar[SEG * DD];
__device__ float g_tokens[BT * DD];
__device__ float g_qkv[BT * 3 * DD];

// split activations
__device__ bf16 g_y_hi[BT * DD];
__device__ bf16 g_y_lo[BT * DD];
__device__ bf16 g_o_hi[BT * DD];
__device__ bf16 g_o_lo[BT * DD];
__device__ bf16 g_m_hi[(size_t)BT * MLPH];
__device__ bf16 g_m_lo[(size_t)BT * MLPH];
__device__ bf16 g_pA_hi[(size_t)TOTPTS * 128];
__device__ bf16 g_pA_lo[(size_t)TOTPTS * 128];

// split+transposed weights [N,K] per layer
__device__ bf16 g_wq_hi[(size_t)DEPTH * 3 * DD * DD];
__device__ bf16 g_wq_lo[(size_t)DEPTH * 3 * DD * DD];
__device__ bf16 g_wp_hi[(size_t)DEPTH * DD * DD];
__device__ bf16 g_wp_lo[(size_t)DEPTH * DD * DD];
__device__ bf16 g_w1_hi[(size_t)DEPTH * MLPH * DD];
__device__ bf16 g_w1_lo[(size_t)DEPTH * MLPH * DD];
__device__ bf16 g_w2_hi[(size_t)DEPTH * DD * MLPH];
__device__ bf16 g_w2_lo[(size_t)DEPTH * DD * MLPH];
__device__ bf16 g_wa_hi[DD * 256];
__device__ bf16 g_wa_lo[DD * 256];

// ---------------- helpers ----------------
__device__ __forceinline__ uint32_t s2u(const void* p) {
    return (uint32_t)__cvta_generic_to_shared(p);
}
#define SWZ64(o) ((o) ^ (((o) >> 3) & 0x30))

__device__ __forceinline__ void cpa16(uint32_t dst, const void* src, bool pred) {
    int sz = pred ? 16 : 0;
    asm volatile("cp.async.cg.shared.global [%0], [%1], 16, %2;"
                 :: "r"(dst), "l"(src), "r"(sz) : "memory");
}
#define CP_COMMIT() asm volatile("cp.async.commit_group;" ::: "memory")
template <int N>
__device__ __forceinline__ void cp_wait() {
    asm volatile("cp.async.wait_group %0;" :: "n"(N) : "memory");
}

__device__ __forceinline__ void ldsm4(uint32_t* r, uint32_t addr) {
    asm volatile("ldmatrix.sync.aligned.m8n8.x4.shared.b16 {%0,%1,%2,%3}, [%4];"
                 : "=r"(r[0]), "=r"(r[1]), "=r"(r[2]), "=r"(r[3]) : "r"(addr));
}
__device__ __forceinline__ void mma16816(float* d, const uint32_t* a, const uint32_t* b) {
    asm volatile(
        "mma.sync.aligned.m16n8k16.row.col.f32.bf16.bf16.f32 "
        "{%0,%1,%2,%3}, {%4,%5,%6,%7}, {%8,%9}, {%0,%1,%2,%3};"
        : "+f"(d[0]), "+f"(d[1]), "+f"(d[2]), "+f"(d[3])
        : "r"(a[0]), "r"(a[1]), "r"(a[2]), "r"(a[3]), "r"(b[0]), "r"(b[1]));
}

__device__ __forceinline__ void split2(float v, bf16& h, bf16& l) {
    h = __float2bfloat16(v);
    l = __float2bfloat16(v - __bfloat162float(h));
}
__device__ __forceinline__ float gelu_exact(float v) {
    return 0.5f * v * (1.0f + erff(v * 0.7071067811865476f));
}

#define NSTG 3
#define STG_BYTES 32768
#define SMEM_GEMM (NSTG * STG_BYTES)

// ---------------- pillar GEMM: A = [pA | split(pooled[cell])], K=256, 128x128 tile ----
__global__ __launch_bounds__(256, 2)
void k_pgemm(const bf16* __restrict__ b_hi, const bf16* __restrict__ b_lo) {
    extern __shared__ char smem[];
    const int tid = threadIdx.x;
    const int lane = tid & 31, wid = tid >> 5;
    const int warpM = (wid & 3) * 32;
    const int warpN = (wid >> 2) * 64;
    const int rowBase = blockIdx.y * 128;
    const int colBase = blockIdx.x * 128;
    const uint32_t sb = s2u(smem);
    const int C = 8;  // K=256

    const int lr0 = tid >> 2, lq = tid & 3;
    uint32_t lso[2];
    size_t aOff[2], bOff[2];
#pragma unroll
    for (int p = 0; p < 2; p++) {
        int r = p * 64 + lr0;
        lso[p] = (uint32_t)(r * 64 + ((lq ^ ((r >> 1) & 3)) << 4));
        aOff[p] = (size_t)(rowBase + r) * 128 + lq * 8;
        bOff[p] = (size_t)(colBase + r) * 256 + lq * 8;
    }

    auto load_chunk = [&](int s, int c) {
        uint32_t base = sb + s * STG_BYTES;
        int k0 = c << 5;
        if (c < 4) {
#pragma unroll
            for (int p = 0; p < 2; p++) {
                cpa16(base + lso[p], g_pA_hi + aOff[p] + k0, true);
                cpa16(base + 8192 + lso[p], g_pA_lo + aOff[p] + k0, true);
            }
        } else {
#pragma unroll
            for (int p4 = 0; p4 < 4; p4++) {
                int r2 = p4 * 32 + (tid >> 3);
                int c4 = tid & 7;
                int cell = g_cell[rowBase + r2];
                float4 v4 = *(const float4*)&g_pooled[(size_t)cell * 128 + (k0 - 128) + c4 * 4];
                bf16 h0, l0, h1, l1, h2, l2, h3, l3;
                split2(v4.x, h0, l0); split2(v4.y, h1, l1);
                split2(v4.z, h2, l2); split2(v4.w, h3, l3);
                uint32_t boff = (uint32_t)(r2 * 64 + ((((c4 >> 1) ^ ((r2 >> 1) & 3)) << 4) + (c4 & 1) * 8));
                __nv_bfloat162 ph0 = __halves2bfloat162(h0, h1);
                __nv_bfloat162 ph1 = __halves2bfloat162(h2, h3);
                __nv_bfloat162 pl0 = __halves2bfloat162(l0, l1);
                __nv_bfloat162 pl1 = __halves2bfloat162(l2, l3);
                uint32_t u0 = *(uint32_t*)&ph0, u1 = *(uint32_t*)&ph1;
                uint32_t w0 = *(uint32_t*)&pl0, w1 = *(uint32_t*)&pl1;
                asm volatile("st.shared.v2.b32 [%0], {%1,%2};" :: "r"(base + boff), "r"(u0), "r"(u1) : "memory");
                asm volatile("st.shared.v2.b32 [%0], {%1,%2};" :: "r"(base + 8192 + boff), "r"(w0), "r"(w1) : "memory");
            }
        }
#pragma unroll
        for (int p = 0; p < 2; p++) {
            cpa16(base + 16384 + lso[p], b_hi + bOff[p] + k0, true);
            cpa16(base + 24576 + lso[p], b_lo + bOff[p] + k0, true);
        }
    };

    float acc[2][8][4];
#pragma unroll
    for (int mt = 0; mt < 2; mt++)
#pragma unroll
        for (int nt = 0; nt < 8; nt++)
#pragma unroll
            for (int q = 0; q < 4; q++) acc[mt][nt][q] = 0.0f;

    load_chunk(0, 0);
    CP_COMMIT();
    load_chunk(1, 1);
    CP_COMMIT();

    const int fi = lane >> 3, fr = lane & 7;
    const int aRowAdd = ((fi & 1) << 3) + fr;
    const int aKb = (fi >> 1) << 4;
    const int bRowAdd = ((fi & 2) << 2) + fr;
    const int bKb = (fi & 1) << 4;

    for (int c = 0; c < C; ++c) {
        cp_wait<1>();
        __syncthreads();
        uint32_t aB = sb + (c % NSTG) * STG_BYTES;
        uint32_t bB = aB + 16384;
#pragma unroll
        for (int ks = 0; ks < 2; ++ks) {
            const int kb = ks * 32;
            uint32_t ah[2][4], al[2][4];
#pragma unroll
            for (int mt = 0; mt < 2; mt++) {
                uint32_t o = SWZ64((uint32_t)((warpM + mt * 16 + aRowAdd) * 64 + kb + aKb));
                ldsm4(ah[mt], aB + o);
                ldsm4(al[mt], aB + 8192 + o);
            }
#pragma unroll
            for (int jp = 0; jp < 4; jp++) {
                uint32_t th[4], tl[4];
                uint32_t o = SWZ64((uint32_t)((warpN + jp * 16 + bRowAdd) * 64 + kb + bKb));
                ldsm4(th, bB + o);
                ldsm4(tl, bB + 8192 + o);
#pragma unroll
                for (int mt = 0; mt < 2; mt++) {
                    mma16816(acc[mt][2 * jp], ah[mt], th);
                    mma16816(acc[mt][2 * jp], ah[mt], tl);
                    mma16816(acc[mt][2 * jp], al[mt], th);
                    mma16816(acc[mt][2 * jp + 1], ah[mt], th + 2);
                    mma16816(acc[mt][2 * jp + 1], ah[mt], tl + 2);
                    mma16816(acc[mt][2 * jp + 1], al[mt], th + 2);
                }
            }
        }
        if (c + 2 < C) load_chunk((c + 2) % NSTG, c + 2);
        CP_COMMIT();
    }

    const int qrow = lane >> 2;
    const int qcol = (lane & 3) * 2;
#pragma unroll
    for (int mt = 0; mt < 2; mt++) {
#pragma unroll
        for (int half = 0; half < 2; half++) {
            int grow = rowBase + warpM + mt * 16 + qrow + half * 8;
            int cell = g_cell[grow];
#pragma unroll
            for (int nt = 0; nt < 8; nt++) {
                int gcol = colBase + warpN + nt * 8 + qcol;
                float v0 = acc[mt][nt][half * 2 + 0];
                float v1 = acc[mt][nt][half * 2 + 1];
                // g_pillar is zero-initialized; atomicMax with <=0 is a no-op
                if (v0 > 0.0f)
                    atomicMax((int*)&g_pillar[(size_t)cell * DD + gcol], __float_as_int(v0));
                if (v1 > 0.0f)
                    atomicMax((int*)&g_pillar[(size_t)cell * DD + gcol + 1], __float_as_int(v1));
            }
        }
    }
}

// ---------------- small-tile GEMM: CTA 64x64, 4 warps (32x32), 4 CTAs/SM ----------------
// MODE 0: cf = v                       (qkv; gridDim.z == 1)
// MODE 1: split-K: atomicAdd into cf (+bias from z==0)   (proj, fc2)
// MODE 2: gelu(v+bias) -> split bf16   (fc1; gridDim.z == 1)
#define STG64 16384
template <int MODE>
__global__ __launch_bounds__(128, 4)
void k_tgemm64(const bf16* __restrict__ a_hi, const bf16* __restrict__ a_lo,
               const bf16* __restrict__ b_hi, const bf16* __restrict__ b_lo,
               const float* __restrict__ bias, float* __restrict__ cf,
               bf16* __restrict__ o_hi, bf16* __restrict__ o_lo,
               int M, int N, int K) {
    extern __shared__ char smem[];
    const int tid = threadIdx.x;
    const int lane = tid & 31, wid = tid >> 5;
    const int warpM = (wid & 1) * 32;
    const int warpN = (wid >> 1) * 32;
    const int rowBase = blockIdx.y * 64;
    const int colBase = blockIdx.x * 64;
    const int z = blockIdx.z;
    const int Keff = K / gridDim.z;
    const int kbase = z * Keff;
    const uint32_t sb = s2u(smem);
    const int C = Keff >> 5;

    uint32_t lso[2];
    bool aok[2];
    size_t aOff[2], bOff[2];
#pragma unroll
    for (int p = 0; p < 2; p++) {
        int idx = p * 128 + tid;
        int r = idx >> 2, q = idx & 3;
        lso[p] = (uint32_t)(r * 64 + ((q ^ ((r >> 1) & 3)) << 4));
        aok[p] = (rowBase + r) < M;
        aOff[p] = (size_t)(rowBase + r) * K + kbase + q * 8;
        bOff[p] = (size_t)(colBase + r) * K + kbase + q * 8;
    }

    auto load_chunk = [&](int s, int k0) {
        uint32_t base = sb + s * STG64;
#pragma unroll
        for (int p = 0; p < 2; p++) {
            cpa16(base + lso[p], a_hi + aOff[p] + k0, aok[p]);
            cpa16(base + 4096 + lso[p], a_lo + aOff[p] + k0, aok[p]);
            cpa16(base + 8192 + lso[p], b_hi + bOff[p] + k0, true);
            cpa16(base + 12288 + lso[p], b_lo + bOff[p] + k0, true);
        }
    };

    float acc[2][4][4];
#pragma unroll
    for (int mt = 0; mt < 2; mt++)
#pragma unroll
        for (int nt = 0; nt < 4; nt++)
#pragma unroll
            for (int q = 0; q < 4; q++) acc[mt][nt][q] = 0.0f;

    load_chunk(0, 0);
    CP_COMMIT();
    load_chunk(1, 32);
    CP_COMMIT();

    const int fi = lane >> 3, fr = lane & 7;
    const int aRowAdd = ((fi & 1) << 3) + fr;
    const int aKb = (fi >> 1) << 4;
    const int bRowAdd = ((fi & 2) << 2) + fr;
    const int bKb = (fi & 1) << 4;

    for (int c = 0; c < C; ++c) {
        cp_wait<1>();
        __syncthreads();
        uint32_t aB = sb + (c % NSTG) * STG64;
        uint32_t bB = aB + 8192;
#pragma unroll
        for (int ks = 0; ks < 2; ++ks) {
            const int kb = ks * 32;
            uint32_t ah[2][4], al[2][4];
#pragma unroll
            for (int mt = 0; mt < 2; mt++) {
                uint32_t o = SWZ64((uint32_t)((warpM + mt * 16 + aRowAdd) * 64 + kb + aKb));
                ldsm4(ah[mt], aB + o);
                ldsm4(al[mt], aB + 4096 + o);
            }
#pragma unroll
            for (int jp = 0; jp < 2; jp++) {
                uint32_t th[4], tl[4];
                uint32_t o = SWZ64((uint32_t)((warpN + jp * 16 + bRowAdd) * 64 + kb + bKb));
                ldsm4(th, bB + o);
                ldsm4(tl, bB + 4096 + o);
#pragma unroll
                for (int mt = 0; mt < 2; mt++) {
                    mma16816(acc[mt][2 * jp], ah[mt], th);
                    mma16816(acc[mt][2 * jp], ah[mt], tl);
                    mma16816(acc[mt][2 * jp], al[mt], th);
                    mma16816(acc[mt][2 * jp + 1], ah[mt], th + 2);
                    mma16816(acc[mt][2 * jp + 1], ah[mt], tl + 2);
                    mma16816(acc[mt][2 * jp + 1], al[mt], th + 2);
                }
            }
        }
        if (c + 2 < C) load_chunk((c + 2) % NSTG, (c + 2) << 5);
        CP_COMMIT();
    }

    const int qrow = lane >> 2;
    const int qcol = (lane & 3) * 2;
#pragma unroll
    for (int mt = 0; mt < 2; mt++) {
#pragma unroll
        for (int half = 0; half < 2; half++) {
            int grow = rowBase + warpM + mt * 16 + qrow + half * 8;
            if (grow >= M) continue;
#pragma unroll
            for (int nt = 0; nt < 4; nt++) {
                int gcol = colBase + warpN + nt * 8 + qcol;
                float d0 = acc[mt][nt][half * 2 + 0];
                float d1 = acc[mt][nt][half * 2 + 1];
                if (MODE == 0) {
                    *(float2*)&cf[(size_t)grow * N + gcol] = make_float2(d0, d1);
                } else if (MODE == 1) {
                    float2 bi = *(const float2*)&bias[gcol];
                    float a0 = d0 + (z == 0 ? bi.x : 0.0f);
                    float a1 = d1 + (z == 0 ? bi.y : 0.0f);
                    atomicAdd(&cf[(size_t)grow * N + gcol], a0);
                    atomicAdd(&cf[(size_t)grow * N + gcol + 1], a1);
                } else {
                    float2 bi = *(const float2*)&bias[gcol];
                    float v0 = gelu_exact(d0 + bi.x);
                    float v1 = gelu_exact(d1 + bi.y);
                    bf16 h0, l0, h1, l1;
                    split2(v0, h0, l0);
                    split2(v1, h1, l1);
                    *(__nv_bfloat162*)&o_hi[(size_t)grow * N + gcol] = __halves2bfloat162(h0, h1);
                    *(__nv_bfloat162*)&o_lo[(size_t)grow * N + gcol] = __halves2bfloat162(l0, l1);
                }
            }
        }
    }
}
#define SMEM_GEMM64 (NSTG * STG64)

// ---------------- weight transpose + split: W[K,N] -> Wt[N,K] hi/lo ------------
// 64-wide K tiles; each thread stores an __nv_bfloat162 -> 128B/warp stores
__global__ void k_wT(const float* __restrict__ W, bf16* __restrict__ hi,
                     bf16* __restrict__ lo, int K, int N) {
    __shared__ float t[64][33];
    int l = blockIdx.z;
    const float* Wl = W + (size_t)l * K * N;
    size_t ob = (size_t)l * K * N;
    int n0 = blockIdx.x * 32, k0 = blockIdx.y * 64;
    int tx = threadIdx.x, ty = threadIdx.y;   // 32 x 8
#pragma unroll
    for (int i = 0; i < 8; i++)
        t[ty + 8 * i][tx] = Wl[(size_t)(k0 + ty + 8 * i) * N + n0 + tx];
    __syncthreads();
#pragma unroll
    for (int i = 0; i < 4; i++) {
        int nl = ty + 8 * i;
        int n = n0 + nl;
        int k = k0 + 2 * tx;
        float v0 = t[2 * tx][nl];
        float v1 = t[2 * tx + 1][nl];
        bf16 h0, l0, h1, l1;
        split2(v0, h0, l0);
        split2(v1, h1, l1);
        *(__nv_bfloat162*)&hi[ob + (size_t)n * K + k] = __halves2bfloat162(h0, h1);
        *(__nv_bfloat162*)&lo[ob + (size_t)n * K + k] = __halves2bfloat162(l0, l1);
    }
}

// ---------------- zero accumulated buffers + Wa transpose/split ----------------
__global__ void k_zero(const float* __restrict__ Wa) {
    int i = blockIdx.x * blockDim.x + threadIdx.x;
    int stride = gridDim.x * blockDim.x;
    for (int t = i; t < SEG; t += stride) g_cnt[t] = 0.0f;
    for (int t = i; t < SEG * 3; t += stride) g_csum[t] = 0.0f;
    for (int t = i; t < SEG * 128; t += stride) g_pooled[t] = 0.0f;
    for (int t = i; t < SEG * DD; t += stride) g_pillar[t] = 0.0f;
    for (int t = i; t < 768 * 256; t += stride) {
        int k = t / 768, n = t - k * 768;
        float v = Wa[(size_t)k * 768 + n];
        bf16 h, l; split2(v, h, l);
        g_wa_hi[(size_t)n * 256 + k] = h;
        g_wa_lo[(size_t)n * 256 + k] = l;
    }
}

// ---------------- cell assignment + centroid sums ----------------
__global__ void k_cell(const float* __restrict__ x) {
    int pt = blockIdx.x * blockDim.x + threadIdx.x;
    if (pt >= TOTPTS) return;
    int b = pt >> 11;
    const float* xp = x + (size_t)pt * 3;
    float y0 = fminf(fmaxf(xp[0] + 1.0f, 0.0f), 1.99f);
    float y1 = fminf(fmaxf(xp[2] + 1.0f, 0.0f), 1.99f);
    int i0 = (int)floorf(y0 / 0.2f);
    int i1 = (int)floorf(y1 / 0.2f);
    int cell = b * (GRID_ * GRID_) + i0 * GRID_ + i1;
    g_cell[pt] = cell;
    atomicAdd(&g_cnt[cell], 1.0f);
    atomicAdd(&g_csum[cell * 3 + 0], xp[1]);
    atomicAdd(&g_csum[cell * 3 + 1], xp[0]);
    atomicAdd(&g_csum[cell * 3 + 2], xp[2]);
}

// ---------------- per-point MLP -> split bf16 pA (vectorized) + pooled segmax ----
__global__ __launch_bounds__(256)
void k_pointmlp(const float* __restrict__ x, const float* __restrict__ W1,
                const float* __restrict__ W2, const float* __restrict__ W3) {
    __shared__ float sW1[6 * 32];
    __shared__ float sW2[32 * 64];
    __shared__ float sW3[64 * 128];
    int tid = threadIdx.x;
    for (int i = tid; i < 6 * 32; i += 256) sW1[i] = W1[i];
    for (int i = tid; i < 32 * 64; i += 256) sW2[i] = W2[i];
    for (int i = tid; i < 64 * 128; i += 256) sW3[i] = W3[i];
    __syncthreads();

    int pt = blockIdx.x * 256 + tid;
    const float* xp = x + (size_t)pt * 3;
    float p0 = xp[1], p1 = xp[0], p2 = xp[2];
    int cell = g_cell[pt];
    float invc = 1.0f / fmaxf(g_cnt[cell], 1.0f);
    float a[6];
    a[0] = p0; a[1] = p1; a[2] = p2;
    a[3] = p0 - g_csum[cell * 3 + 0] * invc;
    a[4] = p1 - g_csum[cell * 3 + 1] * invc;
    a[5] = p2 - g_csum[cell * 3 + 2] * invc;

    float h1[32];
#pragma unroll
    for (int j = 0; j < 32; j++) {
        float s = 0.0f;
#pragma unroll
        for (int i = 0; i < 6; i++) s = fmaf(a[i], sW1[i * 32 + j], s);
        h1[j] = fmaxf(s, 0.0f);
    }
    float h2[64];
#pragma unroll
    for (int j = 0; j < 64; j++) {
        float s = 0.0f;
#pragma unroll
        for (int i = 0; i < 32; i++) s = fmaf(h1[i], sW2[i * 64 + j], s);
        h2[j] = fmaxf(s, 0.0f);
    }
    bf16* pAh = &g_pA_hi[(size_t)pt * 128];
    bf16* pAl = &g_pA_lo[(size_t)pt * 128];
    int* poolI = (int*)&g_pooled[(size_t)cell * 128];
    for (int j8 = 0; j8 < 16; j8++) {
        uint4 hv, lv;
        bf16* hbuf = (bf16*)&hv;
        bf16* lbuf = (bf16*)&lv;
#pragma unroll
        for (int jj = 0; jj < 8; jj++) {
            int j = j8 * 8 + jj;
            float s = 0.0f;
#pragma unroll
            for (int i = 0; i < 64; i++) s = fmaf(h2[i], sW3[i * 128 + j], s);
            s = fmaxf(s, 0.0f);
            bf16 h, l; split2(s, h, l);
            hbuf[jj] = h;
            lbuf[jj] = l;
            // g_pooled zero-initialized; skip no-op atomics
            if (s > 0.0f) atomicMax(&poolI[j], __float_as_int(s));
        }
        *(uint4*)&pAh[j8 * 8] = hv;
        *(uint4*)&pAl[j8 * 8] = lv;
    }
}

// ---------------- token assembly ----------------
__global__ void k_tokens(const float* __restrict__ cls, const float* __restrict__ pos,
                         const float* __restrict__ bng, const float* __restrict__ bnb,
                         const float* __restrict__ bnm, const float* __restrict__ bnv) {
    int idx = blockIdx.x * blockDim.x + threadIdx.x;
    if (idx >= BT * DD) return;
    int row = idx / DD, d = idx - row * DD;
    int b = row / TT, t = row - b * TT;
    float v;
    if (t == 0) {
        v = cls[d];
    } else {
        int tp = t - 1;
        float pv = g_pillar[(size_t)(b * (GRID_ * GRID_) + tp) * DD + d];
        float inv = bng[tp] * rsqrtf(bnv[tp] + EPSLN);
        v = (pv - bnm[tp]) * inv + bnb[tp];
    }
    g_tokens[idx] = v + pos[(size_t)t * DD + d];
}

// ---------------- LayerNorm: warp-per-row ----------------
__global__ __launch_bounds__(256)
void k_ln(const float* __restrict__ src, const float* __restrict__ g,
          const float* __restrict__ bt, bf16* __restrict__ yh, bf16* __restrict__ yl) {
    int lane = threadIdx.x & 31, w = threadIdx.x >> 5;
    int row = blockIdx.x * 8 + w;
    if (row >= BT) return;
    const float4* sp = (const float4*)(src + (size_t)row * DD);
    float4 v[6];
    float sum = 0.0f;
#pragma unroll
    for (int i = 0; i < 6; i++) {
        v[i] = sp[lane + 32 * i];
        sum += v[i].x + v[i].y + v[i].z + v[i].w;
    }
#pragma unroll
    for (int o = 16; o > 0; o >>= 1) sum += __shfl_xor_sync(0xffffffff, sum, o);
    float mean = sum * (1.0f / 768.0f);
    float var = 0.0f;
#pragma unroll
    for (int i = 0; i < 6; i++) {
        float a = v[i].x - mean, b2 = v[i].y - mean, c = v[i].z - mean, d = v[i].w - mean;
        var += a * a + b2 * b2 + c * c + d * d;
    }
#pragma unroll
    for (int o = 16; o > 0; o >>= 1) var += __shfl_xor_sync(0xffffffff, var, o);
    float rs = rsqrtf(var * (1.0f / 768.0f) + EPSLN);
    const float4* gp = (const float4*)g;
    const float4* bp = (const float4*)bt;
    size_t ro = (size_t)row * DD;
#pragma unroll
    for (int i = 0; i < 6; i++) {
        int c4 = lane + 32 * i;
        float4 gg = gp[c4], bb = bp[c4];
        float o0 = (v[i].x - mean) * rs * gg.x + bb.x;
        float o1 = (v[i].y - mean) * rs * gg.y + bb.y;
        float o2 = (v[i].z - mean) * rs * gg.z + bb.z;
        float o3 = (v[i].w - mean) * rs * gg.w + bb.w;
        bf16 h0, l0, h1, l1, h2, l2, h3, l3;
        split2(o0, h0, l0); split2(o1, h1, l1);
        split2(o2, h2, l2); split2(o3, h3, l3);
        *(__nv_bfloat162*)&yh[ro + c4 * 4] = __halves2bfloat162(h0, h1);
        *(__nv_bfloat162*)&yh[ro + c4 * 4 + 2] = __halves2bfloat162(h2, h3);
        *(__nv_bfloat162*)&yl[ro + c4 * 4] = __halves2bfloat162(l0, l1);
        *(__nv_bfloat162*)&yl[ro + c4 * 4 + 2] = __halves2bfloat162(l2, l3);
    }
}

// ---------------- fused attention (float4, conflict-free, 256 threads) ----------------
#define ATT_KST (16 * 104 * 4)
#define ATT_VS  (104 * 64)
#define SMEM_ATTN ((ATT_KST + ATT_VS + 8 * 64 + 8 * 104) * 4)
__global__ __launch_bounds__(256)
void k_attn() {
    extern __shared__ float sm[];
    float4* KsT4 = (float4*)sm;
    float* Vs = sm + ATT_KST;
    float* Qs = Vs + ATT_VS;
    float* Ps = Qs + 8 * 64;
    int bh = blockIdx.x;
    int b = bh / HEADS, h = bh - b * HEADS;
    int tid = threadIdx.x, lane = tid & 31, w = tid >> 5;

    for (int i = tid; i < TT * 16; i += 256) {
        int t = i >> 4, dd = i & 15;
        KsT4[dd * 104 + t] =
            *(const float4*)(g_qkv + (size_t)(b * TT + t) * (3 * DD) + DD + h * 64 + dd * 4);
    }
    for (int i = tid; i < 104 * 64; i += 256) {
        int t = i >> 6, d = i & 63;
        Vs[i] = (t < TT)
            ? g_qkv[(size_t)(b * TT + t) * (3 * DD) + 2 * DD + h * 64 + d] : 0.0f;
    }
    __syncthreads();

    for (int tq = w; tq < TT; tq += 8) {
        size_t qoff = (size_t)(b * TT + tq) * (3 * DD) + h * 64;
        Qs[w * 64 + lane] = g_qkv[qoff + lane];
        Qs[w * 64 + 32 + lane] = g_qkv[qoff + 32 + lane];
        __syncwarp();
        const float4* Qs4 = (const float4*)(Qs + w * 64);
        int jc[4];
        float s[4] = {0.0f, 0.0f, 0.0f, 0.0f};
#pragma unroll
        for (int m = 0; m < 4; m++) {
            int j = lane + 32 * m;
            jc[m] = (j < TT) ? j : 0;
        }
#pragma unroll
        for (int dd = 0; dd < 16; dd++) {
            float4 q = Qs4[dd];
#pragma unroll
            for (int m = 0; m < 4; m++) {
                float4 k = KsT4[dd * 104 + jc[m]];
                s[m] = fmaf(q.x, k.x, s[m]);
                s[m] = fmaf(q.y, k.y, s[m]);
                s[m] = fmaf(q.z, k.z, s[m]);
                s[m] = fmaf(q.w, k.w, s[m]);
            }
        }
#pragma unroll
        for (int m = 0; m < 4; m++)
            s[m] = (lane + 32 * m < TT) ? s[m] * 0.125f : -1e30f;
        float mx = fmaxf(fmaxf(s[0], s[1]), fmaxf(s[2], s[3]));
        for (int o = 16; o > 0; o >>= 1) mx = fmaxf(mx, __shfl_xor_sync(0xffffffff, mx, o));
        float p[4], sum = 0.0f;
#pragma unroll
        for (int m = 0; m < 4; m++) {
            int j = lane + 32 * m;
            p[m] = (j < TT) ? expf(s[m] - mx) : 0.0f;
            sum += p[m];
        }
        for (int o = 16; o > 0; o >>= 1) sum += __shfl_xor_sync(0xffffffff, sum, o);
        float inv = 1.0f / sum;
#pragma unroll
        for (int m = 0; m < 4; m++) {
            int j = lane + 32 * m;
            if (j < 104) Ps[w * 104 + j] = (j < TT) ? p[m] * inv : 0.0f;
        }
        __syncwarp();
        const float4* Ps4 = (const float4*)(Ps + w * 104);
        float a0 = 0.0f, a1 = 0.0f;
#pragma unroll
        for (int j4 = 0; j4 < 26; j4++) {
            float4 pv = Ps4[j4];
            int j = j4 * 4;
            a0 = fmaf(pv.x, Vs[j * 64 + lane], a0);
            a0 = fmaf(pv.y, Vs[(j + 1) * 64 + lane], a0);
            a0 = fmaf(pv.z, Vs[(j + 2) * 64 + lane], a0);
            a0 = fmaf(pv.w, Vs[(j + 3) * 64 + lane], a0);
            a1 = fmaf(pv.x, Vs[j * 64 + 32 + lane], a1);
            a1 = fmaf(pv.y, Vs[(j + 1) * 64 + 32 + lane], a1);
            a1 = fmaf(pv.z, Vs[(j + 2) * 64 + 32 + lane], a1);
            a1 = fmaf(pv.w, Vs[(j + 3) * 64 + 32 + lane], a1);
        }
        size_t ooff = (size_t)(b * TT + tq) * DD + h * 64;
        bf16 hh, ll;
        split2(a0, hh, ll); g_o_hi[ooff + lane] = hh;      g_o_lo[ooff + lane] = ll;
        split2(a1, hh, ll); g_o_hi[ooff + 32 + lane] = hh; g_o_lo[ooff + 32 + lane] = ll;
        __syncwarp();
    }
}

// ---------------- head ----------------
__global__ __launch_bounds__(256)
void k_head(const float* __restrict__ ng, const float* __restrict__ nb,
            const float* __restrict__ hw, const float* __restrict__ hb,
            float* __restrict__ out) {
    __shared__ float red[256];
    __shared__ float yn[768];
    int b = blockIdx.x, tid = threadIdx.x;
    const float* sp = g_tokens + (size_t)(b * TT) * DD;
    float v0 = sp[tid], v1 = sp[tid + 256], v2 = sp[tid + 512];
    red[tid] = v0 + v1 + v2;
    __syncthreads();
    for (int s = 128; s > 0; s >>= 1) {
        if (tid < s) red[tid] += red[tid + s];
        __syncthreads();
    }
    float mean = red[0] * (1.0f / 768.0f);
    __syncthreads();
    float d0 = v0 - mean, d1 = v1 - mean, d2 = v2 - mean;
    red[tid] = d0 * d0 + d1 * d1 + d2 * d2;
    __syncthreads();
    for (int s = 128; s > 0; s >>= 1) {
        if (tid < s) red[tid] += red[tid + s];
        __syncthreads();
    }
    float rs = rsqrtf(red[0] * (1.0f / 768.0f) + EPSLN);
    yn[tid]       = d0 * rs * ng[tid] + nb[tid];
    yn[tid + 256] = d1 * rs * ng[tid + 256] + nb[tid + 256];
    yn[tid + 512] = d2 * rs * ng[tid + 512] + nb[tid + 512];
    __syncthreads();
    if (tid < NCLS) {
        float acc = hb[tid];
        for (int d = 0; d < 768; d++) acc = fmaf(yn[d], hw[d * NCLS + tid], acc);
        out[b * NCLS + tid] = acc;
    }
}

// ---------------- launch ----------------
extern "C" void kernel_launch(void* const* d_in, const int* in_sizes, int n_in,
                              void* d_out, int out_size) {
    const float* x      = (const float*)d_in[0];
    const float* W1     = (const float*)d_in[1];
    const float* W2     = (const float*)d_in[2];
    const float* W3     = (const float*)d_in[3];
    const float* Wa     = (const float*)d_in[4];
    const float* bn_g   = (const float*)d_in[5];
    const float* bn_b   = (const float*)d_in[6];
    const float* bn_m   = (const float*)d_in[7];
    const float* bn_v   = (const float*)d_in[8];
    const float* cls    = (const float*)d_in[9];
    const float* pos    = (const float*)d_in[10];
    const float* ln1_g  = (const float*)d_in[11];
    const float* ln1_b  = (const float*)d_in[12];
    const float* qkv_w  = (const float*)d_in[13];
    const float* proj_w = (const float*)d_in[14];
    const float* proj_b = (const float*)d_in[15];
    const float* ln2_g  = (const float*)d_in[16];
    const float* ln2_b  = (const float*)d_in[17];
    const float* fc1_w  = (const float*)d_in[18];
    const float* fc1_b  = (const float*)d_in[19];
    const float* fc2_w  = (const float*)d_in[20];
    const float* fc2_b  = (const float*)d_in[21];
    const float* norm_g = (const float*)d_in[22];
    const float* norm_b = (const float*)d_in[23];
    const float* head_w = (const float*)d_in[24];
    const float* head_b = (const float*)d_in[25];
    float* out = (float*)d_out;

    cudaFuncSetAttribute(k_pgemm, cudaFuncAttributeMaxDynamicSharedMemorySize, SMEM_GEMM);
    cudaFuncSetAttribute(k_tgemm64<0>, cudaFuncAttributeMaxDynamicSharedMemorySize, SMEM_GEMM64);
    cudaFuncSetAttribute(k_tgemm64<1>, cudaFuncAttributeMaxDynamicSharedMemorySize, SMEM_GEMM64);
    cudaFuncSetAttribute(k_tgemm64<2>, cudaFuncAttributeMaxDynamicSharedMemorySize, SMEM_GEMM64);
    cudaFuncSetAttribute(k_attn, cudaFuncAttributeMaxDynamicSharedMemorySize, SMEM_ATTN);

    float *p_tokens, *p_qkv;
    bf16 *p_y_hi, *p_y_lo, *p_o_hi, *p_o_lo, *p_m_hi, *p_m_lo;
    bf16 *p_wq_hi, *p_wq_lo, *p_wp_hi, *p_wp_lo, *p_w1_hi, *p_w1_lo, *p_w2_hi, *p_w2_lo;
    bf16 *p_wa_hi, *p_wa_lo;
    cudaGetSymbolAddress((void**)&p_tokens, g_tokens);
    cudaGetSymbolAddress((void**)&p_qkv, g_qkv);
    cudaGetSymbolAddress((void**)&p_y_hi, g_y_hi);
    cudaGetSymbolAddress((void**)&p_y_lo, g_y_lo);
    cudaGetSymbolAddress((void**)&p_o_hi, g_o_hi);
    cudaGetSymbolAddress((void**)&p_o_lo, g_o_lo);
    cudaGetSymbolAddress((void**)&p_m_hi, g_m_hi);
    cudaGetSymbolAddress((void**)&p_m_lo, g_m_lo);
    cudaGetSymbolAddress((void**)&p_wq_hi, g_wq_hi);
    cudaGetSymbolAddress((void**)&p_wq_lo, g_wq_lo);
    cudaGetSymbolAddress((void**)&p_wp_hi, g_wp_hi);
    cudaGetSymbolAddress((void**)&p_wp_lo, g_wp_lo);
    cudaGetSymbolAddress((void**)&p_w1_hi, g_w1_hi);
    cudaGetSymbolAddress((void**)&p_w1_lo, g_w1_lo);
    cudaGetSymbolAddress((void**)&p_w2_hi, g_w2_hi);
    cudaGetSymbolAddress((void**)&p_w2_lo, g_w2_lo);
    cudaGetSymbolAddress((void**)&p_wa_hi, g_wa_hi);
    cudaGetSymbolAddress((void**)&p_wa_lo, g_wa_lo);

    dim3 tb(32, 8);

    // ---- pillar stage (k_pgemm at launch index 3 for ncu capture) ----
    k_zero<<<1024, 256>>>(Wa);                          // 0
    k_cell<<<TOTPTS / 256, 256>>>(x);                   // 1
    k_pointmlp<<<TOTPTS / 256, 256>>>(x, W1, W2, W3);   // 2
    k_pgemm<<<dim3(DD / 128, TOTPTS / 128), 256, SMEM_GEMM>>>(p_wa_hi, p_wa_lo);  // 3

    // weight transposes (64-wide K tiles, vectorized bf162 stores)
    k_wT<<<dim3(2304 / 32, 768 / 64, DEPTH), tb>>>(qkv_w, p_wq_hi, p_wq_lo, 768, 2304);
    k_wT<<<dim3(768 / 32, 768 / 64, DEPTH), tb>>>(proj_w, p_wp_hi, p_wp_lo, 768, 768);
    k_wT<<<dim3(3072 / 32, 768 / 64, DEPTH), tb>>>(fc1_w, p_w1_hi, p_w1_lo, 768, 3072);
    k_wT<<<dim3(768 / 32, 3072 / 64, DEPTH), tb>>>(fc2_w, p_w2_hi, p_w2_lo, 3072, 768);

    k_tokens<<<(BT * DD + 255) / 256, 256>>>(cls, pos, bn_g, bn_b, bn_m, bn_v);

    // ---- transformer ----
    const int mtiles64 = (BT + 63) / 64;    // 51
    const int lngrid = (BT + 7) / 8;        // 404
    for (int l = 0; l < DEPTH; l++) {
        k_ln<<<lngrid, 256>>>(p_tokens, ln1_g + (size_t)l * DD, ln1_b + (size_t)l * DD,
                              p_y_hi, p_y_lo);
        k_tgemm64<0><<<dim3(3 * DD / 64, mtiles64, 1), 128, SMEM_GEMM64>>>(
            p_y_hi, p_y_lo, p_wq_hi + (size_t)l * 3 * DD * DD, p_wq_lo + (size_t)l * 3 * DD * DD,
            nullptr, p_qkv, nullptr, nullptr, BT, 3 * DD, DD);
        k_attn<<<BB * HEADS, 256, SMEM_ATTN>>>();
        k_tgemm64<1><<<dim3(DD / 64, mtiles64, 2), 128, SMEM_GEMM64>>>(
            p_o_hi, p_o_lo, p_wp_hi + (size_t)l * DD * DD, p_wp_lo + (size_t)l * DD * DD,
            proj_b + (size_t)l * DD, p_tokens, nullptr, nullptr, BT, DD, DD);
        k_ln<<<lngrid, 256>>>(p_tokens, ln2_g + (size_t)l * DD, ln2_b + (size_t)l * DD,
                              p_y_hi, p_y_lo);
        k_tgemm64<2><<<dim3(MLPH / 64, mtiles64, 1), 128, SMEM_GEMM64>>>(
            p_y_hi, p_y_lo, p_w1_hi + (size_t)l * MLPH * DD, p_w1_lo + (size_t)l * MLPH * DD,
            fc1_b + (size_t)l * MLPH, nullptr, p_m_hi, p_m_lo, BT, MLPH, DD);
        k_tgemm64<1><<<dim3(DD / 64, mtiles64, 3), 128, SMEM_GEMM64>>>(
            p_m_hi, p_m_lo, p_w2_hi + (size_t)l * DD * MLPH, p_w2_lo + (size_t)l * DD * MLPH,
            fc2_b + (size_t)l * DD, p_tokens, nullptr, nullptr, BT, DD, MLPH);
    }

    // ---- head ----
    k_head<<<BB, 256>>>(norm_g, norm_b, head_w, head_b, out);
}

// round 16
// speedup vs baseline: 1.0577x; 1.0577x over previous
#include <cuda_runtime.h>
#include <cuda_bf16.h>
#include <cstdint>

// ---------------- problem constants ----------------
#define BB 32
#define DD 768
#define DEPTH 12
#define HEADS 12
#define GRID_ 10
#define NCLS 40
#define TT 101
#define SEG 3200
#define TOTPTS 65536
#define MLPH 3072
#define BT 3232
#define EPSLN 1e-5f

typedef __nv_bfloat16 bf16;

// ---------------- scratch (device globals) ----------------
__device__ float g_cnt[SEG];
__device__ float g_csum[SEG * 3];
__device__ int   g_cell[TOTPTS];
__device__ float g_pooled[SEG * 128];
__device__ float g_pillar[SEG * DD];
__device__ float g_tokens[BT * DD];
__device__ float g_qkv[BT * 3 * DD];

// split activations
__device__ bf16 g_y_hi[BT * DD];
__device__ bf16 g_y_lo[BT * DD];
__device__ bf16 g_o_hi[BT * DD];
__device__ bf16 g_o_lo[BT * DD];
__device__ bf16 g_m_hi[(size_t)BT * MLPH];
__device__ bf16 g_m_lo[(size_t)BT * MLPH];
__device__ bf16 g_pA_hi[(size_t)TOTPTS * 128];
__device__ bf16 g_pA_lo[(size_t)TOTPTS * 128];

// split+transposed weights [N,K] per layer
__device__ bf16 g_wq_hi[(size_t)DEPTH * 3 * DD * DD];
__device__ bf16 g_wq_lo[(size_t)DEPTH * 3 * DD * DD];
__device__ bf16 g_wp_hi[(size_t)DEPTH * DD * DD];
__device__ bf16 g_wp_lo[(size_t)DEPTH * DD * DD];
__device__ bf16 g_w1_hi[(size_t)DEPTH * MLPH * DD];
__device__ bf16 g_w1_lo[(size_t)DEPTH * MLPH * DD];
__device__ bf16 g_w2_hi[(size_t)DEPTH * DD * MLPH];
__device__ bf16 g_w2_lo[(size_t)DEPTH * DD * MLPH];
__device__ bf16 g_wa_hi[DD * 256];
__device__ bf16 g_wa_lo[DD * 256];

// ---------------- helpers ----------------
__device__ __forceinline__ uint32_t s2u(const void* p) {
    return (uint32_t)__cvta_generic_to_shared(p);
}
#define SWZ64(o) ((o) ^ (((o) >> 3) & 0x30))

__device__ __forceinline__ void cpa16(uint32_t dst, const void* src, bool pred) {
    int sz = pred ? 16 : 0;
    asm volatile("cp.async.cg.shared.global [%0], [%1], 16, %2;"
                 :: "r"(dst), "l"(src), "r"(sz) : "memory");
}
#define CP_COMMIT() asm volatile("cp.async.commit_group;" ::: "memory")
template <int N>
__device__ __forceinline__ void cp_wait() {
    asm volatile("cp.async.wait_group %0;" :: "n"(N) : "memory");
}

__device__ __forceinline__ void ldsm4(uint32_t* r, uint32_t addr) {
    asm volatile("ldmatrix.sync.aligned.m8n8.x4.shared.b16 {%0,%1,%2,%3}, [%4];"
                 : "=r"(r[0]), "=r"(r[1]), "=r"(r[2]), "=r"(r[3]) : "r"(addr));
}
__device__ __forceinline__ void mma16816(float* d, const uint32_t* a, const uint32_t* b) {
    asm volatile(
        "mma.sync.aligned.m16n8k16.row.col.f32.bf16.bf16.f32 "
        "{%0,%1,%2,%3}, {%4,%5,%6,%7}, {%8,%9}, {%0,%1,%2,%3};"
        : "+f"(d[0]), "+f"(d[1]), "+f"(d[2]), "+f"(d[3])
        : "r"(a[0]), "r"(a[1]), "r"(a[2]), "r"(a[3]), "r"(b[0]), "r"(b[1]));
}

__device__ __forceinline__ void split2(float v, bf16& h, bf16& l) {
    h = __float2bfloat16(v);
    l = __float2bfloat16(v - __bfloat162float(h));
}
__device__ __forceinline__ float gelu_exact(float v) {
    return 0.5f * v * (1.0f + erff(v * 0.7071067811865476f));
}

#define NSTG 3
#define STG_BYTES 32768
#define SMEM_GEMM (NSTG * STG_BYTES)

// ---------------- pillar GEMM: A = [pA | split(pooled[cell])], K=256, 128x128 tile ----
__global__ __launch_bounds__(256, 2)
void k_pgemm(const bf16* __restrict__ b_hi, const bf16* __restrict__ b_lo) {
    extern __shared__ char smem[];
    const int tid = threadIdx.x;
    const int lane = tid & 31, wid = tid >> 5;
    const int warpM = (wid & 3) * 32;
    const int warpN = (wid >> 2) * 64;
    const int rowBase = blockIdx.y * 128;
    const int colBase = blockIdx.x * 128;
    const uint32_t sb = s2u(smem);
    const int C = 8;  // K=256

    const int lr0 = tid >> 2, lq = tid & 3;
    uint32_t lso[2];
    size_t aOff[2], bOff[2];
#pragma unroll
    for (int p = 0; p < 2; p++) {
        int r = p * 64 + lr0;
        lso[p] = (uint32_t)(r * 64 + ((lq ^ ((r >> 1) & 3)) << 4));
        aOff[p] = (size_t)(rowBase + r) * 128 + lq * 8;
        bOff[p] = (size_t)(colBase + r) * 256 + lq * 8;
    }

    auto load_chunk = [&](int s, int c) {
        uint32_t base = sb + s * STG_BYTES;
        int k0 = c << 5;
        if (c < 4) {
#pragma unroll
            for (int p = 0; p < 2; p++) {
                cpa16(base + lso[p], g_pA_hi + aOff[p] + k0, true);
                cpa16(base + 8192 + lso[p], g_pA_lo + aOff[p] + k0, true);
            }
        } else {
#pragma unroll
            for (int p4 = 0; p4 < 4; p4++) {
                int r2 = p4 * 32 + (tid >> 3);
                int c4 = tid & 7;
                int cell = g_cell[rowBase + r2];
                float4 v4 = *(const float4*)&g_pooled[(size_t)cell * 128 + (k0 - 128) + c4 * 4];
                bf16 h0, l0, h1, l1, h2, l2, h3, l3;
                split2(v4.x, h0, l0); split2(v4.y, h1, l1);
                split2(v4.z, h2, l2); split2(v4.w, h3, l3);
                uint32_t boff = (uint32_t)(r2 * 64 + ((((c4 >> 1) ^ ((r2 >> 1) & 3)) << 4) + (c4 & 1) * 8));
                __nv_bfloat162 ph0 = __halves2bfloat162(h0, h1);
                __nv_bfloat162 ph1 = __halves2bfloat162(h2, h3);
                __nv_bfloat162 pl0 = __halves2bfloat162(l0, l1);
                __nv_bfloat162 pl1 = __halves2bfloat162(l2, l3);
                uint32_t u0 = *(uint32_t*)&ph0, u1 = *(uint32_t*)&ph1;
                uint32_t w0 = *(uint32_t*)&pl0, w1 = *(uint32_t*)&pl1;
                asm volatile("st.shared.v2.b32 [%0], {%1,%2};" :: "r"(base + boff), "r"(u0), "r"(u1) : "memory");
                asm volatile("st.shared.v2.b32 [%0], {%1,%2};" :: "r"(base + 8192 + boff), "r"(w0), "r"(w1) : "memory");
            }
        }
#pragma unroll
        for (int p = 0; p < 2; p++) {
            cpa16(base + 16384 + lso[p], b_hi + bOff[p] + k0, true);
            cpa16(base + 24576 + lso[p], b_lo + bOff[p] + k0, true);
        }
    };

    float acc[2][8][4];
#pragma unroll
    for (int mt = 0; mt < 2; mt++)
#pragma unroll
        for (int nt = 0; nt < 8; nt++)
#pragma unroll
            for (int q = 0; q < 4; q++) acc[mt][nt][q] = 0.0f;

    load_chunk(0, 0);
    CP_COMMIT();
    load_chunk(1, 1);
    CP_COMMIT();

    const int fi = lane >> 3, fr = lane & 7;
    const int aRowAdd = ((fi & 1) << 3) + fr;
    const int aKb = (fi >> 1) << 4;
    const int bRowAdd = ((fi & 2) << 2) + fr;
    const int bKb = (fi & 1) << 4;

    for (int c = 0; c < C; ++c) {
        cp_wait<1>();
        __syncthreads();
        uint32_t aB = sb + (c % NSTG) * STG_BYTES;
        uint32_t bB = aB + 16384;
#pragma unroll
        for (int ks = 0; ks < 2; ++ks) {
            const int kb = ks * 32;
            uint32_t ah[2][4], al[2][4];
#pragma unroll
            for (int mt = 0; mt < 2; mt++) {
                uint32_t o = SWZ64((uint32_t)((warpM + mt * 16 + aRowAdd) * 64 + kb + aKb));
                ldsm4(ah[mt], aB + o);
                ldsm4(al[mt], aB + 8192 + o);
            }
#pragma unroll
            for (int jp = 0; jp < 4; jp++) {
                uint32_t th[4], tl[4];
                uint32_t o = SWZ64((uint32_t)((warpN + jp * 16 + bRowAdd) * 64 + kb + bKb));
                ldsm4(th, bB + o);
                ldsm4(tl, bB + 8192 + o);
#pragma unroll
                for (int mt = 0; mt < 2; mt++) {
                    mma16816(acc[mt][2 * jp], ah[mt], th);
                    mma16816(acc[mt][2 * jp], ah[mt], tl);
                    mma16816(acc[mt][2 * jp], al[mt], th);
                    mma16816(acc[mt][2 * jp + 1], ah[mt], th + 2);
                    mma16816(acc[mt][2 * jp + 1], ah[mt], tl + 2);
                    mma16816(acc[mt][2 * jp + 1], al[mt], th + 2);
                }
            }
        }
        if (c + 2 < C) load_chunk((c + 2) % NSTG, c + 2);
        CP_COMMIT();
    }

    const int qrow = lane >> 2;
    const int qcol = (lane & 3) * 2;
#pragma unroll
    for (int mt = 0; mt < 2; mt++) {
#pragma unroll
        for (int half = 0; half < 2; half++) {
            int grow = rowBase + warpM + mt * 16 + qrow + half * 8;
            int cell = g_cell[grow];
#pragma unroll
            for (int nt = 0; nt < 8; nt++) {
                int gcol = colBase + warpN + nt * 8 + qcol;
                float v0 = acc[mt][nt][half * 2 + 0];
                float v1 = acc[mt][nt][half * 2 + 1];
                // g_pillar is zero-initialized; atomicMax with <=0 is a no-op
                if (v0 > 0.0f)
                    atomicMax((int*)&g_pillar[(size_t)cell * DD + gcol], __float_as_int(v0));
                if (v1 > 0.0f)
                    atomicMax((int*)&g_pillar[(size_t)cell * DD + gcol + 1], __float_as_int(v1));
            }
        }
    }
}

// ---------------- small-tile GEMM: CTA 64x64, 4 warps (32x32), 4 CTAs/SM ----------------
// MODE 0: cf = v                       (qkv; gridDim.z == 1)
// MODE 1: split-K: atomicAdd into cf (+bias from z==0)   (proj, fc2)
// MODE 2: gelu(v+bias) -> split bf16   (fc1; gridDim.z == 1)
#define STG64 16384
template <int MODE>
__global__ __launch_bounds__(128, 4)
void k_tgemm64(const bf16* __restrict__ a_hi, const bf16* __restrict__ a_lo,
               const bf16* __restrict__ b_hi, const bf16* __restrict__ b_lo,
               const float* __restrict__ bias, float* __restrict__ cf,
               bf16* __restrict__ o_hi, bf16* __restrict__ o_lo,
               int M, int N, int K) {
    extern __shared__ char smem[];
    const int tid = threadIdx.x;
    const int lane = tid & 31, wid = tid >> 5;
    const int warpM = (wid & 1) * 32;
    const int warpN = (wid >> 1) * 32;
    const int rowBase = blockIdx.y * 64;
    const int colBase = blockIdx.x * 64;
    const int z = blockIdx.z;
    const int Keff = K / gridDim.z;
    const int kbase = z * Keff;
    const uint32_t sb = s2u(smem);
    const int C = Keff >> 5;

    uint32_t lso[2];
    bool aok[2];
    size_t aOff[2], bOff[2];
#pragma unroll
    for (int p = 0; p < 2; p++) {
        int idx = p * 128 + tid;
        int r = idx >> 2, q = idx & 3;
        lso[p] = (uint32_t)(r * 64 + ((q ^ ((r >> 1) & 3)) << 4));
        aok[p] = (rowBase + r) < M;
        aOff[p] = (size_t)(rowBase + r) * K + kbase + q * 8;
        bOff[p] = (size_t)(colBase + r) * K + kbase + q * 8;
    }

    auto load_chunk = [&](int s, int k0) {
        uint32_t base = sb + s * STG64;
#pragma unroll
        for (int p = 0; p < 2; p++) {
            cpa16(base + lso[p], a_hi + aOff[p] + k0, aok[p]);
            cpa16(base + 4096 + lso[p], a_lo + aOff[p] + k0, aok[p]);
            cpa16(base + 8192 + lso[p], b_hi + bOff[p] + k0, true);
            cpa16(base + 12288 + lso[p], b_lo + bOff[p] + k0, true);
        }
    };

    float acc[2][4][4];
#pragma unroll
    for (int mt = 0; mt < 2; mt++)
#pragma unroll
        for (int nt = 0; nt < 4; nt++)
#pragma unroll
            for (int q = 0; q < 4; q++) acc[mt][nt][q] = 0.0f;

    load_chunk(0, 0);
    CP_COMMIT();
    load_chunk(1, 32);
    CP_COMMIT();

    const int fi = lane >> 3, fr = lane & 7;
    const int aRowAdd = ((fi & 1) << 3) + fr;
    const int aKb = (fi >> 1) << 4;
    const int bRowAdd = ((fi & 2) << 2) + fr;
    const int bKb = (fi & 1) << 4;

    for (int c = 0; c < C; ++c) {
        cp_wait<1>();
        __syncthreads();
        uint32_t aB = sb + (c % NSTG) * STG64;
        uint32_t bB = aB + 8192;
#pragma unroll
        for (int ks = 0; ks < 2; ++ks) {
            const int kb = ks * 32;
            uint32_t ah[2][4], al[2][4];
#pragma unroll
            for (int mt = 0; mt < 2; mt++) {
                uint32_t o = SWZ64((uint32_t)((warpM + mt * 16 + aRowAdd) * 64 + kb + aKb));
                ldsm4(ah[mt], aB + o);
                ldsm4(al[mt], aB + 4096 + o);
            }
#pragma unroll
            for (int jp = 0; jp < 2; jp++) {
                uint32_t th[4], tl[4];
                uint32_t o = SWZ64((uint32_t)((warpN + jp * 16 + bRowAdd) * 64 + kb + bKb));
                ldsm4(th, bB + o);
                ldsm4(tl, bB + 4096 + o);
#pragma unroll
                for (int mt = 0; mt < 2; mt++) {
                    mma16816(acc[mt][2 * jp], ah[mt], th);
                    mma16816(acc[mt][2 * jp], ah[mt], tl);
                    mma16816(acc[mt][2 * jp], al[mt], th);
                    mma16816(acc[mt][2 * jp + 1], ah[mt], th + 2);
                    mma16816(acc[mt][2 * jp + 1], ah[mt], tl + 2);
                    mma16816(acc[mt][2 * jp + 1], al[mt], th + 2);
                }
            }
        }
        if (c + 2 < C) load_chunk((c + 2) % NSTG, (c + 2) << 5);
        CP_COMMIT();
    }

    const int qrow = lane >> 2;
    const int qcol = (lane & 3) * 2;
#pragma unroll
    for (int mt = 0; mt < 2; mt++) {
#pragma unroll
        for (int half = 0; half < 2; half++) {
            int grow = rowBase + warpM + mt * 16 + qrow + half * 8;
            if (grow >= M) continue;
#pragma unroll
            for (int nt = 0; nt < 4; nt++) {
                int gcol = colBase + warpN + nt * 8 + qcol;
                float d0 = acc[mt][nt][half * 2 + 0];
                float d1 = acc[mt][nt][half * 2 + 1];
                if (MODE == 0) {
                    *(float2*)&cf[(size_t)grow * N + gcol] = make_float2(d0, d1);
                } else if (MODE == 1) {
                    float2 bi = *(const float2*)&bias[gcol];
                    float a0 = d0 + (z == 0 ? bi.x : 0.0f);
                    float a1 = d1 + (z == 0 ? bi.y : 0.0f);
                    atomicAdd(&cf[(size_t)grow * N + gcol], a0);
                    atomicAdd(&cf[(size_t)grow * N + gcol + 1], a1);
                } else {
                    float2 bi = *(const float2*)&bias[gcol];
                    float v0 = gelu_exact(d0 + bi.x);
                    float v1 = gelu_exact(d1 + bi.y);
                    bf16 h0, l0, h1, l1;
                    split2(v0, h0, l0);
                    split2(v1, h1, l1);
                    *(__nv_bfloat162*)&o_hi[(size_t)grow * N + gcol] = __halves2bfloat162(h0, h1);
                    *(__nv_bfloat162*)&o_lo[(size_t)grow * N + gcol] = __halves2bfloat162(l0, l1);
                }
            }
        }
    }
}
#define SMEM_GEMM64 (NSTG * STG64)

// ---------------- weight transpose + split: W[K,N] -> Wt[N,K] hi/lo ------------
// 64-wide K tiles; each thread stores an __nv_bfloat162 -> 128B/warp stores
__global__ void k_wT(const float* __restrict__ W, bf16* __restrict__ hi,
                     bf16* __restrict__ lo, int K, int N) {
    __shared__ float t[64][33];
    int l = blockIdx.z;
    const float* Wl = W + (size_t)l * K * N;
    size_t ob = (size_t)l * K * N;
    int n0 = blockIdx.x * 32, k0 = blockIdx.y * 64;
    int tx = threadIdx.x, ty = threadIdx.y;   // 32 x 8
#pragma unroll
    for (int i = 0; i < 8; i++)
        t[ty + 8 * i][tx] = Wl[(size_t)(k0 + ty + 8 * i) * N + n0 + tx];
    __syncthreads();
#pragma unroll
    for (int i = 0; i < 4; i++) {
        int nl = ty + 8 * i;
        int n = n0 + nl;
        int k = k0 + 2 * tx;
        float v0 = t[2 * tx][nl];
        float v1 = t[2 * tx + 1][nl];
        bf16 h0, l0, h1, l1;
        split2(v0, h0, l0);
        split2(v1, h1, l1);
        *(__nv_bfloat162*)&hi[ob + (size_t)n * K + k] = __halves2bfloat162(h0, h1);
        *(__nv_bfloat162*)&lo[ob + (size_t)n * K + k] = __halves2bfloat162(l0, l1);
    }
}

// ---------------- zero accumulated buffers + Wa transpose/split ----------------
__global__ void k_zero(const float* __restrict__ Wa) {
    int i = blockIdx.x * blockDim.x + threadIdx.x;
    int stride = gridDim.x * blockDim.x;
    for (int t = i; t < SEG; t += stride) g_cnt[t] = 0.0f;
    for (int t = i; t < SEG * 3; t += stride) g_csum[t] = 0.0f;
    for (int t = i; t < SEG * 128; t += stride) g_pooled[t] = 0.0f;
    for (int t = i; t < SEG * DD; t += stride) g_pillar[t] = 0.0f;
    for (int t = i; t < 768 * 256; t += stride) {
        int k = t / 768, n = t - k * 768;
        float v = Wa[(size_t)k * 768 + n];
        bf16 h, l; split2(v, h, l);
        g_wa_hi[(size_t)n * 256 + k] = h;
        g_wa_lo[(size_t)n * 256 + k] = l;
    }
}

// ---------------- cell assignment + centroid sums ----------------
__global__ void k_cell(const float* __restrict__ x) {
    int pt = blockIdx.x * blockDim.x + threadIdx.x;
    if (pt >= TOTPTS) return;
    int b = pt >> 11;
    const float* xp = x + (size_t)pt * 3;
    float y0 = fminf(fmaxf(xp[0] + 1.0f, 0.0f), 1.99f);
    float y1 = fminf(fmaxf(xp[2] + 1.0f, 0.0f), 1.99f);
    int i0 = (int)floorf(y0 / 0.2f);
    int i1 = (int)floorf(y1 / 0.2f);
    int cell = b * (GRID_ * GRID_) + i0 * GRID_ + i1;
    g_cell[pt] = cell;
    atomicAdd(&g_cnt[cell], 1.0f);
    atomicAdd(&g_csum[cell * 3 + 0], xp[1]);
    atomicAdd(&g_csum[cell * 3 + 1], xp[0]);
    atomicAdd(&g_csum[cell * 3 + 2], xp[2]);
}

// ---------------- per-point MLP -> split bf16 pA (paired bf162 stores) + pooled segmax ----
__global__ __launch_bounds__(256)
void k_pointmlp(const float* __restrict__ x, const float* __restrict__ W1,
                const float* __restrict__ W2, const float* __restrict__ W3) {
    __shared__ float sW1[6 * 32];
    __shared__ float sW2[32 * 64];
    __shared__ float sW3[64 * 128];
    int tid = threadIdx.x;
    for (int i = tid; i < 6 * 32; i += 256) sW1[i] = W1[i];
    for (int i = tid; i < 32 * 64; i += 256) sW2[i] = W2[i];
    for (int i = tid; i < 64 * 128; i += 256) sW3[i] = W3[i];
    __syncthreads();

    int pt = blockIdx.x * 256 + tid;
    const float* xp = x + (size_t)pt * 3;
    float p0 = xp[1], p1 = xp[0], p2 = xp[2];
    int cell = g_cell[pt];
    float invc = 1.0f / fmaxf(g_cnt[cell], 1.0f);
    float a[6];
    a[0] = p0; a[1] = p1; a[2] = p2;
    a[3] = p0 - g_csum[cell * 3 + 0] * invc;
    a[4] = p1 - g_csum[cell * 3 + 1] * invc;
    a[5] = p2 - g_csum[cell * 3 + 2] * invc;

    float h1[32];
#pragma unroll
    for (int j = 0; j < 32; j++) {
        float s = 0.0f;
#pragma unroll
        for (int i = 0; i < 6; i++) s = fmaf(a[i], sW1[i * 32 + j], s);
        h1[j] = fmaxf(s, 0.0f);
    }
    float h2[64];
#pragma unroll
    for (int j = 0; j < 64; j++) {
        float s = 0.0f;
#pragma unroll
        for (int i = 0; i < 32; i++) s = fmaf(h1[i], sW2[i * 64 + j], s);
        h2[j] = fmaxf(s, 0.0f);
    }
    bf16* pAh = &g_pA_hi[(size_t)pt * 128];
    bf16* pAl = &g_pA_lo[(size_t)pt * 128];
    int* poolI = (int*)&g_pooled[(size_t)cell * 128];
    for (int j = 0; j < 128; j += 2) {
        float s0 = 0.0f, s1 = 0.0f;
#pragma unroll
        for (int i = 0; i < 64; i++) {
            s0 = fmaf(h2[i], sW3[i * 128 + j], s0);
            s1 = fmaf(h2[i], sW3[i * 128 + j + 1], s1);
        }
        s0 = fmaxf(s0, 0.0f);
        s1 = fmaxf(s1, 0.0f);
        bf16 h0v, l0v, h1v, l1v;
        split2(s0, h0v, l0v);
        split2(s1, h1v, l1v);
        *(__nv_bfloat162*)&pAh[j] = __halves2bfloat162(h0v, h1v);
        *(__nv_bfloat162*)&pAl[j] = __halves2bfloat162(l0v, l1v);
        // g_pooled zero-initialized; skip no-op atomics
        if (s0 > 0.0f) atomicMax(&poolI[j], __float_as_int(s0));
        if (s1 > 0.0f) atomicMax(&poolI[j + 1], __float_as_int(s1));
    }
}

// ---------------- token assembly ----------------
__global__ void k_tokens(const float* __restrict__ cls, const float* __restrict__ pos,
                         const float* __restrict__ bng, const float* __restrict__ bnb,
                         const float* __restrict__ bnm, const float* __restrict__ bnv) {
    int idx = blockIdx.x * blockDim.x + threadIdx.x;
    if (idx >= BT * DD) return;
    int row = idx / DD, d = idx - row * DD;
    int b = row / TT, t = row - b * TT;
    float v;
    if (t == 0) {
        v = cls[d];
    } else {
        int tp = t - 1;
        float pv = g_pillar[(size_t)(b * (GRID_ * GRID_) + tp) * DD + d];
        float inv = bng[tp] * rsqrtf(bnv[tp] + EPSLN);
        v = (pv - bnm[tp]) * inv + bnb[tp];
    }
    g_tokens[idx] = v + pos[(size_t)t * DD + d];
}

// ---------------- LayerNorm: warp-per-row ----------------
__global__ __launch_bounds__(256)
void k_ln(const float* __restrict__ src, const float* __restrict__ g,
          const float* __restrict__ bt, bf16* __restrict__ yh, bf16* __restrict__ yl) {
    int lane = threadIdx.x & 31, w = threadIdx.x >> 5;
    int row = blockIdx.x * 8 + w;
    if (row >= BT) return;
    const float4* sp = (const float4*)(src + (size_t)row * DD);
    float4 v[6];
    float sum = 0.0f;
#pragma unroll
    for (int i = 0; i < 6; i++) {
        v[i] = sp[lane + 32 * i];
        sum += v[i].x + v[i].y + v[i].z + v[i].w;
    }
#pragma unroll
    for (int o = 16; o > 0; o >>= 1) sum += __shfl_xor_sync(0xffffffff, sum, o);
    float mean = sum * (1.0f / 768.0f);
    float var = 0.0f;
#pragma unroll
    for (int i = 0; i < 6; i++) {
        float a = v[i].x - mean, b2 = v[i].y - mean, c = v[i].z - mean, d = v[i].w - mean;
        var += a * a + b2 * b2 + c * c + d * d;
    }
#pragma unroll
    for (int o = 16; o > 0; o >>= 1) var += __shfl_xor_sync(0xffffffff, var, o);
    float rs = rsqrtf(var * (1.0f / 768.0f) + EPSLN);
    const float4* gp = (const float4*)g;
    const float4* bp = (const float4*)bt;
    size_t ro = (size_t)row * DD;
#pragma unroll
    for (int i = 0; i < 6; i++) {
        int c4 = lane + 32 * i;
        float4 gg = gp[c4], bb = bp[c4];
        float o0 = (v[i].x - mean) * rs * gg.x + bb.x;
        float o1 = (v[i].y - mean) * rs * gg.y + bb.y;
        float o2 = (v[i].z - mean) * rs * gg.z + bb.z;
        float o3 = (v[i].w - mean) * rs * gg.w + bb.w;
        bf16 h0, l0, h1, l1, h2, l2, h3, l3;
        split2(o0, h0, l0); split2(o1, h1, l1);
        split2(o2, h2, l2); split2(o3, h3, l3);
        *(__nv_bfloat162*)&yh[ro + c4 * 4] = __halves2bfloat162(h0, h1);
        *(__nv_bfloat162*)&yh[ro + c4 * 4 + 2] = __halves2bfloat162(h2, h3);
        *(__nv_bfloat162*)&yl[ro + c4 * 4] = __halves2bfloat162(l0, l1);
        *(__nv_bfloat162*)&yl[ro + c4 * 4 + 2] = __halves2bfloat162(l2, l3);
    }
}

// ---------------- fused attention (float4, conflict-free, 256 threads) ----------------
#define ATT_KST (16 * 104 * 4)
#define ATT_VS  (104 * 64)
#define SMEM_ATTN ((ATT_KST + ATT_VS + 8 * 64 + 8 * 104) * 4)
__global__ __launch_bounds__(256)
void k_attn() {
    extern __shared__ float sm[];
    float4* KsT4 = (float4*)sm;
    float* Vs = sm + ATT_KST;
    float* Qs = Vs + ATT_VS;
    float* Ps = Qs + 8 * 64;
    int bh = blockIdx.x;
    int b = bh / HEADS, h = bh - b * HEADS;
    int tid = threadIdx.x, lane = tid & 31, w = tid >> 5;

    for (int i = tid; i < TT * 16; i += 256) {
        int t = i >> 4, dd = i & 15;
        KsT4[dd * 104 + t] =
            *(const float4*)(g_qkv + (size_t)(b * TT + t) * (3 * DD) + DD + h * 64 + dd * 4);
    }
    for (int i = tid; i < 104 * 64; i += 256) {
        int t = i >> 6, d = i & 63;
        Vs[i] = (t < TT)
            ? g_qkv[(size_t)(b * TT + t) * (3 * DD) + 2 * DD + h * 64 + d] : 0.0f;
    }
    __syncthreads();

    for (int tq = w; tq < TT; tq += 8) {
        size_t qoff = (size_t)(b * TT + tq) * (3 * DD) + h * 64;
        Qs[w * 64 + lane] = g_qkv[qoff + lane];
        Qs[w * 64 + 32 + lane] = g_qkv[qoff + 32 + lane];
        __syncwarp();
        const float4* Qs4 = (const float4*)(Qs + w * 64);
        int jc[4];
        float s[4] = {0.0f, 0.0f, 0.0f, 0.0f};
#pragma unroll
        for (int m = 0; m < 4; m++) {
            int j = lane + 32 * m;
            jc[m] = (j < TT) ? j : 0;
        }
#pragma unroll
        for (int dd = 0; dd < 16; dd++) {
            float4 q = Qs4[dd];
#pragma unroll
            for (int m = 0; m < 4; m++) {
                float4 k = KsT4[dd * 104 + jc[m]];
                s[m] = fmaf(q.x, k.x, s[m]);
                s[m] = fmaf(q.y, k.y, s[m]);
                s[m] = fmaf(q.z, k.z, s[m]);
                s[m] = fmaf(q.w, k.w, s[m]);
            }
        }
#pragma unroll
        for (int m = 0; m < 4; m++)
            s[m] = (lane + 32 * m < TT) ? s[m] * 0.125f : -1e30f;
        float mx = fmaxf(fmaxf(s[0], s[1]), fmaxf(s[2], s[3]));
        for (int o = 16; o > 0; o >>= 1) mx = fmaxf(mx, __shfl_xor_sync(0xffffffff, mx, o));
        float p[4], sum = 0.0f;
#pragma unroll
        for (int m = 0; m < 4; m++) {
            int j = lane + 32 * m;
            p[m] = (j < TT) ? expf(s[m] - mx) : 0.0f;
            sum += p[m];
        }
        for (int o = 16; o > 0; o >>= 1) sum += __shfl_xor_sync(0xffffffff, sum, o);
        float inv = 1.0f / sum;
#pragma unroll
        for (int m = 0; m < 4; m++) {
            int j = lane + 32 * m;
            if (j < 104) Ps[w * 104 + j] = (j < TT) ? p[m] * inv : 0.0f;
        }
        __syncwarp();
        const float4* Ps4 = (const float4*)(Ps + w * 104);
        float a0 = 0.0f, a1 = 0.0f;
#pragma unroll
        for (int j4 = 0; j4 < 26; j4++) {
            float4 pv = Ps4[j4];
            int j = j4 * 4;
            a0 = fmaf(pv.x, Vs[j * 64 + lane], a0);
            a0 = fmaf(pv.y, Vs[(j + 1) * 64 + lane], a0);
            a0 = fmaf(pv.z, Vs[(j + 2) * 64 + lane], a0);
            a0 = fmaf(pv.w, Vs[(j + 3) * 64 + lane], a0);
            a1 = fmaf(pv.x, Vs[j * 64 + 32 + lane], a1);
            a1 = fmaf(pv.y, Vs[(j + 1) * 64 + 32 + lane], a1);
            a1 = fmaf(pv.z, Vs[(j + 2) * 64 + 32 + lane], a1);
            a1 = fmaf(pv.w, Vs[(j + 3) * 64 + 32 + lane], a1);
        }
        size_t ooff = (size_t)(b * TT + tq) * DD + h * 64;
        bf16 hh, ll;
        split2(a0, hh, ll); g_o_hi[ooff + lane] = hh;      g_o_lo[ooff + lane] = ll;
        split2(a1, hh, ll); g_o_hi[ooff + 32 + lane] = hh; g_o_lo[ooff + 32 + lane] = ll;
        __syncwarp();
    }
}

// ---------------- head ----------------
__global__ __launch_bounds__(256)
void k_head(const float* __restrict__ ng, const float* __restrict__ nb,
            const float* __restrict__ hw, const float* __restrict__ hb,
            float* __restrict__ out) {
    __shared__ float red[256];
    __shared__ float yn[768];
    int b = blockIdx.x, tid = threadIdx.x;
    const float* sp = g_tokens + (size_t)(b * TT) * DD;
    float v0 = sp[tid], v1 = sp[tid + 256], v2 = sp[tid + 512];
    red[tid] = v0 + v1 + v2;
    __syncthreads();
    for (int s = 128; s > 0; s >>= 1) {
        if (tid < s) red[tid] += red[tid + s];
        __syncthreads();
    }
    float mean = red[0] * (1.0f / 768.0f);
    __syncthreads();
    float d0 = v0 - mean, d1 = v1 - mean, d2 = v2 - mean;
    red[tid] = d0 * d0 + d1 * d1 + d2 * d2;
    __syncthreads();
    for (int s = 128; s > 0; s >>= 1) {
        if (tid < s) red[tid] += red[tid + s];
        __syncthreads();
    }
    float rs = rsqrtf(red[0] * (1.0f / 768.0f) + EPSLN);
    yn[tid]       = d0 * rs * ng[tid] + nb[tid];
    yn[tid + 256] = d1 * rs * ng[tid + 256] + nb[tid + 256];
    yn[tid + 512] = d2 * rs * ng[tid + 512] + nb[tid + 512];
    __syncthreads();
    if (tid < NCLS) {
        float acc = hb[tid];
        for (int d = 0; d < 768; d++) acc = fmaf(yn[d], hw[d * NCLS + tid], acc);
        out[b * NCLS + tid] = acc;
    }
}

// ---------------- launch ----------------
extern "C" void kernel_launch(void* const* d_in, const int* in_sizes, int n_in,
                              void* d_out, int out_size) {
    const float* x      = (const float*)d_in[0];
    const float* W1     = (const float*)d_in[1];
    const float* W2     = (const float*)d_in[2];
    const float* W3     = (const float*)d_in[3];
    const float* Wa     = (const float*)d_in[4];
    const float* bn_g   = (const float*)d_in[5];
    const float* bn_b   = (const float*)d_in[6];
    const float* bn_m   = (const float*)d_in[7];
    const float* bn_v   = (const float*)d_in[8];
    const float* cls    = (const float*)d_in[9];
    const float* pos    = (const float*)d_in[10];
    const float* ln1_g  = (const float*)d_in[11];
    const float* ln1_b  = (const float*)d_in[12];
    const float* qkv_w  = (const float*)d_in[13];
    const float* proj_w = (const float*)d_in[14];
    const float* proj_b = (const float*)d_in[15];
    const float* ln2_g  = (const float*)d_in[16];
    const float* ln2_b  = (const float*)d_in[17];
    const float* fc1_w  = (const float*)d_in[18];
    const float* fc1_b  = (const float*)d_in[19];
    const float* fc2_w  = (const float*)d_in[20];
    const float* fc2_b  = (const float*)d_in[21];
    const float* norm_g = (const float*)d_in[22];
    const float* norm_b = (const float*)d_in[23];
    const float* head_w = (const float*)d_in[24];
    const float* head_b = (const float*)d_in[25];
    float* out = (float*)d_out;

    cudaFuncSetAttribute(k_pgemm, cudaFuncAttributeMaxDynamicSharedMemorySize, SMEM_GEMM);
    cudaFuncSetAttribute(k_tgemm64<0>, cudaFuncAttributeMaxDynamicSharedMemorySize, SMEM_GEMM64);
    cudaFuncSetAttribute(k_tgemm64<1>, cudaFuncAttributeMaxDynamicSharedMemorySize, SMEM_GEMM64);
    cudaFuncSetAttribute(k_tgemm64<2>, cudaFuncAttributeMaxDynamicSharedMemorySize, SMEM_GEMM64);
    cudaFuncSetAttribute(k_attn, cudaFuncAttributeMaxDynamicSharedMemorySize, SMEM_ATTN);

    float *p_tokens, *p_qkv;
    bf16 *p_y_hi, *p_y_lo, *p_o_hi, *p_o_lo, *p_m_hi, *p_m_lo;
    bf16 *p_wq_hi, *p_wq_lo, *p_wp_hi, *p_wp_lo, *p_w1_hi, *p_w1_lo, *p_w2_hi, *p_w2_lo;
    bf16 *p_wa_hi, *p_wa_lo;
    cudaGetSymbolAddress((void**)&p_tokens, g_tokens);
    cudaGetSymbolAddress((void**)&p_qkv, g_qkv);
    cudaGetSymbolAddress((void**)&p_y_hi, g_y_hi);
    cudaGetSymbolAddress((void**)&p_y_lo, g_y_lo);
    cudaGetSymbolAddress((void**)&p_o_hi, g_o_hi);
    cudaGetSymbolAddress((void**)&p_o_lo, g_o_lo);
    cudaGetSymbolAddress((void**)&p_m_hi, g_m_hi);
    cudaGetSymbolAddress((void**)&p_m_lo, g_m_lo);
    cudaGetSymbolAddress((void**)&p_wq_hi, g_wq_hi);
    cudaGetSymbolAddress((void**)&p_wq_lo, g_wq_lo);
    cudaGetSymbolAddress((void**)&p_wp_hi, g_wp_hi);
    cudaGetSymbolAddress((void**)&p_wp_lo, g_wp_lo);
    cudaGetSymbolAddress((void**)&p_w1_hi, g_w1_hi);
    cudaGetSymbolAddress((void**)&p_w1_lo, g_w1_lo);
    cudaGetSymbolAddress((void**)&p_w2_hi, g_w2_hi);
    cudaGetSymbolAddress((void**)&p_w2_lo, g_w2_lo);
    cudaGetSymbolAddress((void**)&p_wa_hi, g_wa_hi);
    cudaGetSymbolAddress((void**)&p_wa_lo, g_wa_lo);

    dim3 tb(32, 8);

    // ---- pillar stage (k_pgemm at launch index 3 for ncu capture) ----
    k_zero<<<1024, 256>>>(Wa);                          // 0
    k_cell<<<TOTPTS / 256, 256>>>(x);                   // 1
    k_pointmlp<<<TOTPTS / 256, 256>>>(x, W1, W2, W3);   // 2
    k_pgemm<<<dim3(DD / 128, TOTPTS / 128), 256, SMEM_GEMM>>>(p_wa_hi, p_wa_lo);  // 3

    // weight transposes (64-wide K tiles, vectorized bf162 stores)
    k_wT<<<dim3(2304 / 32, 768 / 64, DEPTH), tb>>>(qkv_w, p_wq_hi, p_wq_lo, 768, 2304);
    k_wT<<<dim3(768 / 32, 768 / 64, DEPTH), tb>>>(proj_w, p_wp_hi, p_wp_lo, 768, 768);
    k_wT<<<dim3(3072 / 32, 768 / 64, DEPTH), tb>>>(fc1_w, p_w1_hi, p_w1_lo, 768, 3072);
    k_wT<<<dim3(768 / 32, 3072 / 64, DEPTH), tb>>>(fc2_w, p_w2_hi, p_w2_lo, 3072, 768);

    k_tokens<<<(BT * DD + 255) / 256, 256>>>(cls, pos, bn_g, bn_b, bn_m, bn_v);

    // ---- transformer ----
    const int mtiles64 = (BT + 63) / 64;    // 51
    const int lngrid = (BT + 7) / 8;        // 404
    for (int l = 0; l < DEPTH; l++) {
        k_ln<<<lngrid, 256>>>(p_tokens, ln1_g + (size_t)l * DD, ln1_b + (size_t)l * DD,
                              p_y_hi, p_y_lo);
        k_tgemm64<0><<<dim3(3 * DD / 64, mtiles64, 1), 128, SMEM_GEMM64>>>(
            p_y_hi, p_y_lo, p_wq_hi + (size_t)l * 3 * DD * DD, p_wq_lo + (size_t)l * 3 * DD * DD,
            nullptr, p_qkv, nullptr, nullptr, BT, 3 * DD, DD);
        k_attn<<<BB * HEADS, 256, SMEM_ATTN>>>();
        k_tgemm64<1><<<dim3(DD / 64, mtiles64, 2), 128, SMEM_GEMM64>>>(
            p_o_hi, p_o_lo, p_wp_hi + (size_t)l * DD * DD, p_wp_lo + (size_t)l * DD * DD,
            proj_b + (size_t)l * DD, p_tokens, nullptr, nullptr, BT, DD, DD);
        k_ln<<<lngrid, 256>>>(p_tokens, ln2_g + (size_t)l * DD, ln2_b + (size_t)l * DD,
                              p_y_hi, p_y_lo);
        k_tgemm64<2><<<dim3(MLPH / 64, mtiles64, 1), 128, SMEM_GEMM64>>>(
            p_y_hi, p_y_lo, p_w1_hi + (size_t)l * MLPH * DD, p_w1_lo + (size_t)l * MLPH * DD,
            fc1_b + (size_t)l * MLPH, nullptr, p_m_hi, p_m_lo, BT, MLPH, DD);
        k_tgemm64<1><<<dim3(DD / 64, mtiles64, 3), 128, SMEM_GEMM64>>>(
            p_m_hi, p_m_lo, p_w2_hi + (size_t)l * DD * MLPH, p_w2_lo + (size_t)l * DD * MLPH,
            fc2_b + (size_t)l * DD, p_tokens, nullptr, nullptr, BT, DD, MLPH);
    }

    // ---- head ----
    k_head<<<BB, 256>>>(norm_g, norm_b, head_w, head_b, out);
}

// round 17
// speedup vs baseline: 1.0611x; 1.0031x over previous
#include <cuda_runtime.h>
#include <cuda_bf16.h>
#include <cstdint>

// ---------------- problem constants ----------------
#define BB 32
#define DD 768
#define DEPTH 12
#define HEADS 12
#define GRID_ 10
#define NCLS 40
#define TT 101
#define SEG 3200
#define TOTPTS 65536
#define MLPH 3072
#define BT 3232
#define EPSLN 1e-5f

typedef __nv_bfloat16 bf16;

// ---------------- scratch (device globals) ----------------
__device__ float g_cnt[SEG];
__device__ float g_csum[SEG * 3];
__device__ int   g_cell[TOTPTS];
__device__ float g_pooled[SEG * 128];
__device__ float g_pillar[SEG * DD];
__device__ float g_tokens[BT * DD];
__device__ float g_qkv[BT * 3 * DD];

// split activations
__device__ bf16 g_y_hi[BT * DD];
__device__ bf16 g_y_lo[BT * DD];
__device__ bf16 g_o_hi[BT * DD];
__device__ bf16 g_o_lo[BT * DD];
__device__ bf16 g_m_hi[(size_t)BT * MLPH];
__device__ bf16 g_m_lo[(size_t)BT * MLPH];
__device__ bf16 g_pA_hi[(size_t)TOTPTS * 128];
__device__ bf16 g_pA_lo[(size_t)TOTPTS * 128];

// split+transposed weights [N,K] per layer
__device__ bf16 g_wq_hi[(size_t)DEPTH * 3 * DD * DD];
__device__ bf16 g_wq_lo[(size_t)DEPTH * 3 * DD * DD];
__device__ bf16 g_wp_hi[(size_t)DEPTH * DD * DD];
__device__ bf16 g_wp_lo[(size_t)DEPTH * DD * DD];
__device__ bf16 g_w1_hi[(size_t)DEPTH * MLPH * DD];
__device__ bf16 g_w1_lo[(size_t)DEPTH * MLPH * DD];
__device__ bf16 g_w2_hi[(size_t)DEPTH * DD * MLPH];
__device__ bf16 g_w2_lo[(size_t)DEPTH * DD * MLPH];
__device__ bf16 g_wa_hi[DD * 256];
__device__ bf16 g_wa_lo[DD * 256];

// ---------------- helpers ----------------
__device__ __forceinline__ uint32_t s2u(const void* p) {
    return (uint32_t)__cvta_generic_to_shared(p);
}
#define SWZ64(o) ((o) ^ (((o) >> 3) & 0x30))

__device__ __forceinline__ void cpa16(uint32_t dst, const void* src, bool pred) {
    int sz = pred ? 16 : 0;
    asm volatile("cp.async.cg.shared.global [%0], [%1], 16, %2;"
                 :: "r"(dst), "l"(src), "r"(sz) : "memory");
}
#define CP_COMMIT() asm volatile("cp.async.commit_group;" ::: "memory")
template <int N>
__device__ __forceinline__ void cp_wait() {
    asm volatile("cp.async.wait_group %0;" :: "n"(N) : "memory");
}

__device__ __forceinline__ void ldsm4(uint32_t* r, uint32_t addr) {
    asm volatile("ldmatrix.sync.aligned.m8n8.x4.shared.b16 {%0,%1,%2,%3}, [%4];"
                 : "=r"(r[0]), "=r"(r[1]), "=r"(r[2]), "=r"(r[3]) : "r"(addr));
}
__device__ __forceinline__ void mma16816(float* d, const uint32_t* a, const uint32_t* b) {
    asm volatile(
        "mma.sync.aligned.m16n8k16.row.col.f32.bf16.bf16.f32 "
        "{%0,%1,%2,%3}, {%4,%5,%6,%7}, {%8,%9}, {%0,%1,%2,%3};"
        : "+f"(d[0]), "+f"(d[1]), "+f"(d[2]), "+f"(d[3])
        : "r"(a[0]), "r"(a[1]), "r"(a[2]), "r"(a[3]), "r"(b[0]), "r"(b[1]));
}

__device__ __forceinline__ void split2(float v, bf16& h, bf16& l) {
    h = __float2bfloat16(v);
    l = __float2bfloat16(v - __bfloat162float(h));
}
__device__ __forceinline__ float gelu_exact(float v) {
    return 0.5f * v * (1.0f + erff(v * 0.7071067811865476f));
}

#define NSTG 3
#define STG_BYTES 32768
#define SMEM_GEMM (NSTG * STG_BYTES)

// ---------------- pillar GEMM: A = [pA | split(pooled[cell])], K=256, 128x128 tile ----
__global__ __launch_bounds__(256, 2)
void k_pgemm(const bf16* __restrict__ b_hi, const bf16* __restrict__ b_lo) {
    extern __shared__ char smem[];
    const int tid = threadIdx.x;
    const int lane = tid & 31, wid = tid >> 5;
    const int warpM = (wid & 3) * 32;
    const int warpN = (wid >> 2) * 64;
    const int rowBase = blockIdx.y * 128;
    const int colBase = blockIdx.x * 128;
    const uint32_t sb = s2u(smem);
    const int C = 8;  // K=256

    const int lr0 = tid >> 2, lq = tid & 3;
    uint32_t lso[2];
    size_t aOff[2], bOff[2];
#pragma unroll
    for (int p = 0; p < 2; p++) {
        int r = p * 64 + lr0;
        lso[p] = (uint32_t)(r * 64 + ((lq ^ ((r >> 1) & 3)) << 4));
        aOff[p] = (size_t)(rowBase + r) * 128 + lq * 8;
        bOff[p] = (size_t)(colBase + r) * 256 + lq * 8;
    }

    auto load_chunk = [&](int s, int c) {
        uint32_t base = sb + s * STG_BYTES;
        int k0 = c << 5;
        if (c < 4) {
#pragma unroll
            for (int p = 0; p < 2; p++) {
                cpa16(base + lso[p], g_pA_hi + aOff[p] + k0, true);
                cpa16(base + 8192 + lso[p], g_pA_lo + aOff[p] + k0, true);
            }
        } else {
#pragma unroll
            for (int p4 = 0; p4 < 4; p4++) {
                int r2 = p4 * 32 + (tid >> 3);
                int c4 = tid & 7;
                int cell = g_cell[rowBase + r2];
                float4 v4 = *(const float4*)&g_pooled[(size_t)cell * 128 + (k0 - 128) + c4 * 4];
                bf16 h0, l0, h1, l1, h2, l2, h3, l3;
                split2(v4.x, h0, l0); split2(v4.y, h1, l1);
                split2(v4.z, h2, l2); split2(v4.w, h3, l3);
                uint32_t boff = (uint32_t)(r2 * 64 + ((((c4 >> 1) ^ ((r2 >> 1) & 3)) << 4) + (c4 & 1) * 8));
                __nv_bfloat162 ph0 = __halves2bfloat162(h0, h1);
                __nv_bfloat162 ph1 = __halves2bfloat162(h2, h3);
                __nv_bfloat162 pl0 = __halves2bfloat162(l0, l1);
                __nv_bfloat162 pl1 = __halves2bfloat162(l2, l3);
                uint32_t u0 = *(uint32_t*)&ph0, u1 = *(uint32_t*)&ph1;
                uint32_t w0 = *(uint32_t*)&pl0, w1 = *(uint32_t*)&pl1;
                asm volatile("st.shared.v2.b32 [%0], {%1,%2};" :: "r"(base + boff), "r"(u0), "r"(u1) : "memory");
                asm volatile("st.shared.v2.b32 [%0], {%1,%2};" :: "r"(base + 8192 + boff), "r"(w0), "r"(w1) : "memory");
            }
        }
#pragma unroll
        for (int p = 0; p < 2; p++) {
            cpa16(base + 16384 + lso[p], b_hi + bOff[p] + k0, true);
            cpa16(base + 24576 + lso[p], b_lo + bOff[p] + k0, true);
        }
    };

    float acc[2][8][4];
#pragma unroll
    for (int mt = 0; mt < 2; mt++)
#pragma unroll
        for (int nt = 0; nt < 8; nt++)
#pragma unroll
            for (int q = 0; q < 4; q++) acc[mt][nt][q] = 0.0f;

    load_chunk(0, 0);
    CP_COMMIT();
    load_chunk(1, 1);
    CP_COMMIT();

    const int fi = lane >> 3, fr = lane & 7;
    const int aRowAdd = ((fi & 1) << 3) + fr;
    const int aKb = (fi >> 1) << 4;
    const int bRowAdd = ((fi & 2) << 2) + fr;
    const int bKb = (fi & 1) << 4;

    for (int c = 0; c < C; ++c) {
        cp_wait<1>();
        __syncthreads();
        uint32_t aB = sb + (c % NSTG) * STG_BYTES;
        uint32_t bB = aB + 16384;
#pragma unroll
        for (int ks = 0; ks < 2; ++ks) {
            const int kb = ks * 32;
            uint32_t ah[2][4], al[2][4];
#pragma unroll
            for (int mt = 0; mt < 2; mt++) {
                uint32_t o = SWZ64((uint32_t)((warpM + mt * 16 + aRowAdd) * 64 + kb + aKb));
                ldsm4(ah[mt], aB + o);
                ldsm4(al[mt], aB + 8192 + o);
            }
#pragma unroll
            for (int jp = 0; jp < 4; jp++) {
                uint32_t th[4], tl[4];
                uint32_t o = SWZ64((uint32_t)((warpN + jp * 16 + bRowAdd) * 64 + kb + bKb));
                ldsm4(th, bB + o);
                ldsm4(tl, bB + 8192 + o);
#pragma unroll
                for (int mt = 0; mt < 2; mt++) {
                    mma16816(acc[mt][2 * jp], ah[mt], th);
                    mma16816(acc[mt][2 * jp], ah[mt], tl);
                    mma16816(acc[mt][2 * jp], al[mt], th);
                    mma16816(acc[mt][2 * jp + 1], ah[mt], th + 2);
                    mma16816(acc[mt][2 * jp + 1], ah[mt], tl + 2);
                    mma16816(acc[mt][2 * jp + 1], al[mt], th + 2);
                }
            }
        }
        if (c + 2 < C) load_chunk((c + 2) % NSTG, c + 2);
        CP_COMMIT();
    }

    const int qrow = lane >> 2;
    const int qcol = (lane & 3) * 2;
#pragma unroll
    for (int mt = 0; mt < 2; mt++) {
#pragma unroll
        for (int half = 0; half < 2; half++) {
            int grow = rowBase + warpM + mt * 16 + qrow + half * 8;
            int cell = g_cell[grow];
#pragma unroll
            for (int nt = 0; nt < 8; nt++) {
                int gcol = colBase + warpN + nt * 8 + qcol;
                float v0 = acc[mt][nt][half * 2 + 0];
                float v1 = acc[mt][nt][half * 2 + 1];
                // g_pillar is zero-initialized; atomicMax with <=0 is a no-op
                if (v0 > 0.0f)
                    atomicMax((int*)&g_pillar[(size_t)cell * DD + gcol], __float_as_int(v0));
                if (v1 > 0.0f)
                    atomicMax((int*)&g_pillar[(size_t)cell * DD + gcol + 1], __float_as_int(v1));
            }
        }
    }
}

// ---------------- small-tile GEMM: CTA 64x64, 4 warps (32x32), 4 CTAs/SM ----------------
// MODE 0: cf = v                       (qkv; gridDim.z == 1)
// MODE 1: split-K: atomicAdd into cf (+bias from z==0)   (proj, fc2)
// MODE 2: gelu(v+bias) -> split bf16   (fc1; gridDim.z == 1)
#define STG64 16384
template <int MODE>
__global__ __launch_bounds__(128, 4)
void k_tgemm64(const bf16* __restrict__ a_hi, const bf16* __restrict__ a_lo,
               const bf16* __restrict__ b_hi, const bf16* __restrict__ b_lo,
               const float* __restrict__ bias, float* __restrict__ cf,
               bf16* __restrict__ o_hi, bf16* __restrict__ o_lo,
               int M, int N, int K) {
    extern __shared__ char smem[];
    const int tid = threadIdx.x;
    const int lane = tid & 31, wid = tid >> 5;
    const int warpM = (wid & 1) * 32;
    const int warpN = (wid >> 1) * 32;
    const int rowBase = blockIdx.y * 64;
    const int colBase = blockIdx.x * 64;
    const int z = blockIdx.z;
    const int Keff = K / gridDim.z;
    const int kbase = z * Keff;
    const uint32_t sb = s2u(smem);
    const int C = Keff >> 5;

    uint32_t lso[2];
    bool aok[2];
    size_t aOff[2], bOff[2];
#pragma unroll
    for (int p = 0; p < 2; p++) {
        int idx = p * 128 + tid;
        int r = idx >> 2, q = idx & 3;
        lso[p] = (uint32_t)(r * 64 + ((q ^ ((r >> 1) & 3)) << 4));
        aok[p] = (rowBase + r) < M;
        aOff[p] = (size_t)(rowBase + r) * K + kbase + q * 8;
        bOff[p] = (size_t)(colBase + r) * K + kbase + q * 8;
    }

    auto load_chunk = [&](int s, int k0) {
        uint32_t base = sb + s * STG64;
#pragma unroll
        for (int p = 0; p < 2; p++) {
            cpa16(base + lso[p], a_hi + aOff[p] + k0, aok[p]);
            cpa16(base + 4096 + lso[p], a_lo + aOff[p] + k0, aok[p]);
            cpa16(base + 8192 + lso[p], b_hi + bOff[p] + k0, true);
            cpa16(base + 12288 + lso[p], b_lo + bOff[p] + k0, true);
        }
    };

    float acc[2][4][4];
#pragma unroll
    for (int mt = 0; mt < 2; mt++)
#pragma unroll
        for (int nt = 0; nt < 4; nt++)
#pragma unroll
            for (int q = 0; q < 4; q++) acc[mt][nt][q] = 0.0f;

    load_chunk(0, 0);
    CP_COMMIT();
    load_chunk(1, 32);
    CP_COMMIT();

    const int fi = lane >> 3, fr = lane & 7;
    const int aRowAdd = ((fi & 1) << 3) + fr;
    const int aKb = (fi >> 1) << 4;
    const int bRowAdd = ((fi & 2) << 2) + fr;
    const int bKb = (fi & 1) << 4;

    for (int c = 0; c < C; ++c) {
        cp_wait<1>();
        __syncthreads();
        uint32_t aB = sb + (c % NSTG) * STG64;
        uint32_t bB = aB + 8192;
#pragma unroll
        for (int ks = 0; ks < 2; ++ks) {
            const int kb = ks * 32;
            uint32_t ah[2][4], al[2][4];
#pragma unroll
            for (int mt = 0; mt < 2; mt++) {
                uint32_t o = SWZ64((uint32_t)((warpM + mt * 16 + aRowAdd) * 64 + kb + aKb));
                ldsm4(ah[mt], aB + o);
                ldsm4(al[mt], aB + 4096 + o);
            }
#pragma unroll
            for (int jp = 0; jp < 2; jp++) {
                uint32_t th[4], tl[4];
                uint32_t o = SWZ64((uint32_t)((warpN + jp * 16 + bRowAdd) * 64 + kb + bKb));
                ldsm4(th, bB + o);
                ldsm4(tl, bB + 4096 + o);
#pragma unroll
                for (int mt = 0; mt < 2; mt++) {
                    mma16816(acc[mt][2 * jp], ah[mt], th);
                    mma16816(acc[mt][2 * jp], ah[mt], tl);
                    mma16816(acc[mt][2 * jp], al[mt], th);
                    mma16816(acc[mt][2 * jp + 1], ah[mt], th + 2);
                    mma16816(acc[mt][2 * jp + 1], ah[mt], tl + 2);
                    mma16816(acc[mt][2 * jp + 1], al[mt], th + 2);
                }
            }
        }
        if (c + 2 < C) load_chunk((c + 2) % NSTG, (c + 2) << 5);
        CP_COMMIT();
    }

    const int qrow = lane >> 2;
    const int qcol = (lane & 3) * 2;
#pragma unroll
    for (int mt = 0; mt < 2; mt++) {
#pragma unroll
        for (int half = 0; half < 2; half++) {
            int grow = rowBase + warpM + mt * 16 + qrow + half * 8;
            if (grow >= M) continue;
#pragma unroll
            for (int nt = 0; nt < 4; nt++) {
                int gcol = colBase + warpN + nt * 8 + qcol;
                float d0 = acc[mt][nt][half * 2 + 0];
                float d1 = acc[mt][nt][half * 2 + 1];
                if (MODE == 0) {
                    *(float2*)&cf[(size_t)grow * N + gcol] = make_float2(d0, d1);
                } else if (MODE == 1) {
                    float2 bi = *(const float2*)&bias[gcol];
                    float a0 = d0 + (z == 0 ? bi.x : 0.0f);
                    float a1 = d1 + (z == 0 ? bi.y : 0.0f);
                    atomicAdd(&cf[(size_t)grow * N + gcol], a0);
                    atomicAdd(&cf[(size_t)grow * N + gcol + 1], a1);
                } else {
                    float2 bi = *(const float2*)&bias[gcol];
                    float v0 = gelu_exact(d0 + bi.x);
                    float v1 = gelu_exact(d1 + bi.y);
                    bf16 h0, l0, h1, l1;
                    split2(v0, h0, l0);
                    split2(v1, h1, l1);
                    *(__nv_bfloat162*)&o_hi[(size_t)grow * N + gcol] = __halves2bfloat162(h0, h1);
                    *(__nv_bfloat162*)&o_lo[(size_t)grow * N + gcol] = __halves2bfloat162(l0, l1);
                }
            }
        }
    }
}
#define SMEM_GEMM64 (NSTG * STG64)

// ---------------- weight transpose + split: W[K,N] -> Wt[N,K] hi/lo ------------
__global__ void k_wT(const float* __restrict__ W, bf16* __restrict__ hi,
                     bf16* __restrict__ lo, int K, int N) {
    __shared__ float t[64][33];
    int l = blockIdx.z;
    const float* Wl = W + (size_t)l * K * N;
    size_t ob = (size_t)l * K * N;
    int n0 = blockIdx.x * 32, k0 = blockIdx.y * 64;
    int tx = threadIdx.x, ty = threadIdx.y;   // 32 x 8
#pragma unroll
    for (int i = 0; i < 8; i++)
        t[ty + 8 * i][tx] = Wl[(size_t)(k0 + ty + 8 * i) * N + n0 + tx];
    __syncthreads();
#pragma unroll
    for (int i = 0; i < 4; i++) {
        int nl = ty + 8 * i;
        int n = n0 + nl;
        int k = k0 + 2 * tx;
        float v0 = t[2 * tx][nl];
        float v1 = t[2 * tx + 1][nl];
        bf16 h0, l0, h1, l1;
        split2(v0, h0, l0);
        split2(v1, h1, l1);
        *(__nv_bfloat162*)&hi[ob + (size_t)n * K + k] = __halves2bfloat162(h0, h1);
        *(__nv_bfloat162*)&lo[ob + (size_t)n * K + k] = __halves2bfloat162(l0, l1);
    }
}

// ---------------- zero accumulated buffers + Wa transpose/split ----------------
__global__ void k_zero(const float* __restrict__ Wa) {
    int i = blockIdx.x * blockDim.x + threadIdx.x;
    int stride = gridDim.x * blockDim.x;
    for (int t = i; t < SEG; t += stride) g_cnt[t] = 0.0f;
    for (int t = i; t < SEG * 3; t += stride) g_csum[t] = 0.0f;
    for (int t = i; t < SEG * 128; t += stride) g_pooled[t] = 0.0f;
    for (int t = i; t < SEG * DD; t += stride) g_pillar[t] = 0.0f;
    for (int t = i; t < 768 * 256; t += stride) {
        int k = t / 768, n = t - k * 768;
        float v = Wa[(size_t)k * 768 + n];
        bf16 h, l; split2(v, h, l);
        g_wa_hi[(size_t)n * 256 + k] = h;
        g_wa_lo[(size_t)n * 256 + k] = l;
    }
}

// ---------------- cell assignment + centroid sums ----------------
__global__ void k_cell(const float* __restrict__ x) {
    int pt = blockIdx.x * blockDim.x + threadIdx.x;
    if (pt >= TOTPTS) return;
    int b = pt >> 11;
    const float* xp = x + (size_t)pt * 3;
    float y0 = fminf(fmaxf(xp[0] + 1.0f, 0.0f), 1.99f);
    float y1 = fminf(fmaxf(xp[2] + 1.0f, 0.0f), 1.99f);
    int i0 = (int)floorf(y0 / 0.2f);
    int i1 = (int)floorf(y1 / 0.2f);
    int cell = b * (GRID_ * GRID_) + i0 * GRID_ + i1;
    g_cell[pt] = cell;
    atomicAdd(&g_cnt[cell], 1.0f);
    atomicAdd(&g_csum[cell * 3 + 0], xp[1]);
    atomicAdd(&g_csum[cell * 3 + 1], xp[0]);
    atomicAdd(&g_csum[cell * 3 + 2], xp[2]);
}

// ---------------- per-point MLP -> split bf16 pA (paired bf162 stores) + pooled segmax ----
__global__ __launch_bounds__(256)
void k_pointmlp(const float* __restrict__ x, const float* __restrict__ W1,
                const float* __restrict__ W2, const float* __restrict__ W3) {
    __shared__ float sW1[6 * 32];
    __shared__ float sW2[32 * 64];
    __shared__ float sW3[64 * 128];
    int tid = threadIdx.x;
    for (int i = tid; i < 6 * 32; i += 256) sW1[i] = W1[i];
    for (int i = tid; i < 32 * 64; i += 256) sW2[i] = W2[i];
    for (int i = tid; i < 64 * 128; i += 256) sW3[i] = W3[i];
    __syncthreads();

    int pt = blockIdx.x * 256 + tid;
    const float* xp = x + (size_t)pt * 3;
    float p0 = xp[1], p1 = xp[0], p2 = xp[2];
    int cell = g_cell[pt];
    float invc = 1.0f / fmaxf(g_cnt[cell], 1.0f);
    float a[6];
    a[0] = p0; a[1] = p1; a[2] = p2;
    a[3] = p0 - g_csum[cell * 3 + 0] * invc;
    a[4] = p1 - g_csum[cell * 3 + 1] * invc;
    a[5] = p2 - g_csum[cell * 3 + 2] * invc;

    float h1[32];
#pragma unroll
    for (int j = 0; j < 32; j++) {
        float s = 0.0f;
#pragma unroll
        for (int i = 0; i < 6; i++) s = fmaf(a[i], sW1[i * 32 + j], s);
        h1[j] = fmaxf(s, 0.0f);
    }
    float h2[64];
#pragma unroll
    for (int j = 0; j < 64; j++) {
        float s = 0.0f;
#pragma unroll
        for (int i = 0; i < 32; i++) s = fmaf(h1[i], sW2[i * 64 + j], s);
        h2[j] = fmaxf(s, 0.0f);
    }
    bf16* pAh = &g_pA_hi[(size_t)pt * 128];
    bf16* pAl = &g_pA_lo[(size_t)pt * 128];
    int* poolI = (int*)&g_pooled[(size_t)cell * 128];
    for (int j = 0; j < 128; j += 2) {
        float s0 = 0.0f, s1 = 0.0f;
#pragma unroll
        for (int i = 0; i < 64; i++) {
            s0 = fmaf(h2[i], sW3[i * 128 + j], s0);
            s1 = fmaf(h2[i], sW3[i * 128 + j + 1], s1);
        }
        s0 = fmaxf(s0, 0.0f);
        s1 = fmaxf(s1, 0.0f);
        bf16 h0v, l0v, h1v, l1v;
        split2(s0, h0v, l0v);
        split2(s1, h1v, l1v);
        *(__nv_bfloat162*)&pAh[j] = __halves2bfloat162(h0v, h1v);
        *(__nv_bfloat162*)&pAl[j] = __halves2bfloat162(l0v, l1v);
        if (s0 > 0.0f) atomicMax(&poolI[j], __float_as_int(s0));
        if (s1 > 0.0f) atomicMax(&poolI[j + 1], __float_as_int(s1));
    }
}

// ---------------- token assembly ----------------
__global__ void k_tokens(const float* __restrict__ cls, const float* __restrict__ pos,
                         const float* __restrict__ bng, const float* __restrict__ bnb,
                         const float* __restrict__ bnm, const float* __restrict__ bnv) {
    int idx = blockIdx.x * blockDim.x + threadIdx.x;
    if (idx >= BT * DD) return;
    int row = idx / DD, d = idx - row * DD;
    int b = row / TT, t = row - b * TT;
    float v;
    if (t == 0) {
        v = cls[d];
    } else {
        int tp = t - 1;
        float pv = g_pillar[(size_t)(b * (GRID_ * GRID_) + tp) * DD + d];
        float inv = bng[tp] * rsqrtf(bnv[tp] + EPSLN);
        v = (pv - bnm[tp]) * inv + bnb[tp];
    }
    g_tokens[idx] = v + pos[(size_t)t * DD + d];
}

// ---------------- LayerNorm: warp-per-row ----------------
__global__ __launch_bounds__(256)
void k_ln(const float* __restrict__ src, const float* __restrict__ g,
          const float* __restrict__ bt, bf16* __restrict__ yh, bf16* __restrict__ yl) {
    int lane = threadIdx.x & 31, w = threadIdx.x >> 5;
    int row = blockIdx.x * 8 + w;
    if (row >= BT) return;
    const float4* sp = (const float4*)(src + (size_t)row * DD);
    float4 v[6];
    float sum = 0.0f;
#pragma unroll
    for (int i = 0; i < 6; i++) {
        v[i] = sp[lane + 32 * i];
        sum += v[i].x + v[i].y + v[i].z + v[i].w;
    }
#pragma unroll
    for (int o = 16; o > 0; o >>= 1) sum += __shfl_xor_sync(0xffffffff, sum, o);
    float mean = sum * (1.0f / 768.0f);
    float var = 0.0f;
#pragma unroll
    for (int i = 0; i < 6; i++) {
        float a = v[i].x - mean, b2 = v[i].y - mean, c = v[i].z - mean, d = v[i].w - mean;
        var += a * a + b2 * b2 + c * c + d * d;
    }
#pragma unroll
    for (int o = 16; o > 0; o >>= 1) var += __shfl_xor_sync(0xffffffff, var, o);
    float rs = rsqrtf(var * (1.0f / 768.0f) + EPSLN);
    const float4* gp = (const float4*)g;
    const float4* bp = (const float4*)bt;
    size_t ro = (size_t)row * DD;
#pragma unroll
    for (int i = 0; i < 6; i++) {
        int c4 = lane + 32 * i;
        float4 gg = gp[c4], bb = bp[c4];
        float o0 = (v[i].x - mean) * rs * gg.x + bb.x;
        float o1 = (v[i].y - mean) * rs * gg.y + bb.y;
        float o2 = (v[i].z - mean) * rs * gg.z + bb.z;
        float o3 = (v[i].w - mean) * rs * gg.w + bb.w;
        bf16 h0, l0, h1, l1, h2, l2, h3, l3;
        split2(o0, h0, l0); split2(o1, h1, l1);
        split2(o2, h2, l2); split2(o3, h3, l3);
        *(__nv_bfloat162*)&yh[ro + c4 * 4] = __halves2bfloat162(h0, h1);
        *(__nv_bfloat162*)&yh[ro + c4 * 4 + 2] = __halves2bfloat162(h2, h3);
        *(__nv_bfloat162*)&yl[ro + c4 * 4] = __halves2bfloat162(l0, l1);
        *(__nv_bfloat162*)&yl[ro + c4 * 4 + 2] = __halves2bfloat162(l2, l3);
    }
}

// ---------------- fused attention (float4 scores, paired P@V, 256 threads) ----------------
#define ATT_KST (16 * 104 * 4)
#define ATT_VS  (104 * 64)
#define SMEM_ATTN ((ATT_KST + ATT_VS + 8 * 64 + 8 * 104) * 4)
__global__ __launch_bounds__(256)
void k_attn() {
    extern __shared__ float sm[];
    float4* KsT4 = (float4*)sm;
    float* Vs = sm + ATT_KST;
    float* Qs = Vs + ATT_VS;
    float* Ps = Qs + 8 * 64;
    int bh = blockIdx.x;
    int b = bh / HEADS, h = bh - b * HEADS;
    int tid = threadIdx.x, lane = tid & 31, w = tid >> 5;

    for (int i = tid; i < TT * 16; i += 256) {
        int t = i >> 4, dd = i & 15;
        KsT4[dd * 104 + t] =
            *(const float4*)(g_qkv + (size_t)(b * TT + t) * (3 * DD) + DD + h * 64 + dd * 4);
    }
    for (int i = tid; i < 104 * 64; i += 256) {
        int t = i >> 6, d = i & 63;
        Vs[i] = (t < TT)
            ? g_qkv[(size_t)(b * TT + t) * (3 * DD) + 2 * DD + h * 64 + d] : 0.0f;
    }
    __syncthreads();

    for (int tq = w; tq < TT; tq += 8) {
        size_t qoff = (size_t)(b * TT + tq) * (3 * DD) + h * 64;
        Qs[w * 64 + lane] = g_qkv[qoff + lane];
        Qs[w * 64 + 32 + lane] = g_qkv[qoff + 32 + lane];
        __syncwarp();
        const float4* Qs4 = (const float4*)(Qs + w * 64);
        int jc[4];
        float s[4] = {0.0f, 0.0f, 0.0f, 0.0f};
#pragma unroll
        for (int m = 0; m < 4; m++) {
            int j = lane + 32 * m;
            jc[m] = (j < TT) ? j : 0;
        }
#pragma unroll
        for (int dd = 0; dd < 16; dd++) {
            float4 q = Qs4[dd];
#pragma unroll
            for (int m = 0; m < 4; m++) {
                float4 k = KsT4[dd * 104 + jc[m]];
                s[m] = fmaf(q.x, k.x, s[m]);
                s[m] = fmaf(q.y, k.y, s[m]);
                s[m] = fmaf(q.z, k.z, s[m]);
                s[m] = fmaf(q.w, k.w, s[m]);
            }
        }
#pragma unroll
        for (int m = 0; m < 4; m++)
            s[m] = (lane + 32 * m < TT) ? s[m] * 0.125f : -1e30f;
        float mx = fmaxf(fmaxf(s[0], s[1]), fmaxf(s[2], s[3]));
        for (int o = 16; o > 0; o >>= 1) mx = fmaxf(mx, __shfl_xor_sync(0xffffffff, mx, o));
        float p[4], sum = 0.0f;
#pragma unroll
        for (int m = 0; m < 4; m++) {
            int j = lane + 32 * m;
            p[m] = (j < TT) ? expf(s[m] - mx) : 0.0f;
            sum += p[m];
        }
        for (int o = 16; o > 0; o >>= 1) sum += __shfl_xor_sync(0xffffffff, sum, o);
        float inv = 1.0f / sum;
#pragma unroll
        for (int m = 0; m < 4; m++) {
            int j = lane + 32 * m;
            if (j < 104) Ps[w * 104 + j] = (j < TT) ? p[m] * inv : 0.0f;
        }
        __syncwarp();
        // O = P @ V; lane owns column pair (2*lane, 2*lane+1)
        const float4* Ps4 = (const float4*)(Ps + w * 104);
        const float2* Vs2 = (const float2*)Vs;   // row stride 32 float2
        float a0 = 0.0f, a1 = 0.0f;
#pragma unroll
        for (int j4 = 0; j4 < 26; j4++) {
            float4 pv = Ps4[j4];
            int j = j4 * 4;
            float2 v0 = Vs2[j * 32 + lane];
            float2 v1 = Vs2[(j + 1) * 32 + lane];
            float2 v2 = Vs2[(j + 2) * 32 + lane];
            float2 v3 = Vs2[(j + 3) * 32 + lane];
            a0 = fmaf(pv.x, v0.x, a0); a1 = fmaf(pv.x, v0.y, a1);
            a0 = fmaf(pv.y, v1.x, a0); a1 = fmaf(pv.y, v1.y, a1);
            a0 = fmaf(pv.z, v2.x, a0); a1 = fmaf(pv.z, v2.y, a1);
            a0 = fmaf(pv.w, v3.x, a0); a1 = fmaf(pv.w, v3.y, a1);
        }
        size_t ooff = (size_t)(b * TT + tq) * DD + h * 64 + 2 * lane;
        bf16 h0v, l0v, h1v, l1v;
        split2(a0, h0v, l0v);
        split2(a1, h1v, l1v);
        *(__nv_bfloat162*)&g_o_hi[ooff] = __halves2bfloat162(h0v, h1v);
        *(__nv_bfloat162*)&g_o_lo[ooff] = __halves2bfloat162(l0v, l1v);
        __syncwarp();
    }
}

// ---------------- head ----------------
__global__ __launch_bounds__(256)
void k_head(const float* __restrict__ ng, const float* __restrict__ nb,
            const float* __restrict__ hw, const float* __restrict__ hb,
            float* __restrict__ out) {
    __shared__ float red[256];
    __shared__ float yn[768];
    int b = blockIdx.x, tid = threadIdx.x;
    const float* sp = g_tokens + (size_t)(b * TT) * DD;
    float v0 = sp[tid], v1 = sp[tid + 256], v2 = sp[tid + 512];
    red[tid] = v0 + v1 + v2;
    __syncthreads();
    for (int s = 128; s > 0; s >>= 1) {
        if (tid < s) red[tid] += red[tid + s];
        __syncthreads();
    }
    float mean = red[0] * (1.0f / 768.0f);
    __syncthreads();
    float d0 = v0 - mean, d1 = v1 - mean, d2 = v2 - mean;
    red[tid] = d0 * d0 + d1 * d1 + d2 * d2;
    __syncthreads();
    for (int s = 128; s > 0; s >>= 1) {
        if (tid < s) red[tid] += red[tid + s];
        __syncthreads();
    }
    float rs = rsqrtf(red[0] * (1.0f / 768.0f) + EPSLN);
    yn[tid]       = d0 * rs * ng[tid] + nb[tid];
    yn[tid + 256] = d1 * rs * ng[tid + 256] + nb[tid + 256];
    yn[tid + 512] = d2 * rs * ng[tid + 512] + nb[tid + 512];
    __syncthreads();
    if (tid < NCLS) {
        float acc = hb[tid];
        for (int d = 0; d < 768; d++) acc = fmaf(yn[d], hw[d * NCLS + tid], acc);
        out[b * NCLS + tid] = acc;
    }
}

// ---------------- launch ----------------
extern "C" void kernel_launch(void* const* d_in, const int* in_sizes, int n_in,
                              void* d_out, int out_size) {
    const float* x      = (const float*)d_in[0];
    const float* W1     = (const float*)d_in[1];
    const float* W2     = (const float*)d_in[2];
    const float* W3     = (const float*)d_in[3];
    const float* Wa     = (const float*)d_in[4];
    const float* bn_g   = (const float*)d_in[5];
    const float* bn_b   = (const float*)d_in[6];
    const float* bn_m   = (const float*)d_in[7];
    const float* bn_v   = (const float*)d_in[8];
    const float* cls    = (const float*)d_in[9];
    const float* pos    = (const float*)d_in[10];
    const float* ln1_g  = (const float*)d_in[11];
    const float* ln1_b  = (const float*)d_in[12];
    const float* qkv_w  = (const float*)d_in[13];
    const float* proj_w = (const float*)d_in[14];
    const float* proj_b = (const float*)d_in[15];
    const float* ln2_g  = (const float*)d_in[16];
    const float* ln2_b  = (const float*)d_in[17];
    const float* fc1_w  = (const float*)d_in[18];
    const float* fc1_b  = (const float*)d_in[19];
    const float* fc2_w  = (const float*)d_in[20];
    const float* fc2_b  = (const float*)d_in[21];
    const float* norm_g = (const float*)d_in[22];
    const float* norm_b = (const float*)d_in[23];
    const float* head_w = (const float*)d_in[24];
    const float* head_b = (const float*)d_in[25];
    float* out = (float*)d_out;

    cudaFuncSetAttribute(k_pgemm, cudaFuncAttributeMaxDynamicSharedMemorySize, SMEM_GEMM);
    cudaFuncSetAttribute(k_tgemm64<0>, cudaFuncAttributeMaxDynamicSharedMemorySize, SMEM_GEMM64);
    cudaFuncSetAttribute(k_tgemm64<1>, cudaFuncAttributeMaxDynamicSharedMemorySize, SMEM_GEMM64);
    cudaFuncSetAttribute(k_tgemm64<2>, cudaFuncAttributeMaxDynamicSharedMemorySize, SMEM_GEMM64);
    cudaFuncSetAttribute(k_attn, cudaFuncAttributeMaxDynamicSharedMemorySize, SMEM_ATTN);

    float *p_tokens, *p_qkv;
    bf16 *p_y_hi, *p_y_lo, *p_o_hi, *p_o_lo, *p_m_hi, *p_m_lo;
    bf16 *p_wq_hi, *p_wq_lo, *p_wp_hi, *p_wp_lo, *p_w1_hi, *p_w1_lo, *p_w2_hi, *p_w2_lo;
    bf16 *p_wa_hi, *p_wa_lo;
    cudaGetSymbolAddress((void**)&p_tokens, g_tokens);
    cudaGetSymbolAddress((void**)&p_qkv, g_qkv);
    cudaGetSymbolAddress((void**)&p_y_hi, g_y_hi);
    cudaGetSymbolAddress((void**)&p_y_lo, g_y_lo);
    cudaGetSymbolAddress((void**)&p_o_hi, g_o_hi);
    cudaGetSymbolAddress((void**)&p_o_lo, g_o_lo);
    cudaGetSymbolAddress((void**)&p_m_hi, g_m_hi);
    cudaGetSymbolAddress((void**)&p_m_lo, g_m_lo);
    cudaGetSymbolAddress((void**)&p_wq_hi, g_wq_hi);
    cudaGetSymbolAddress((void**)&p_wq_lo, g_wq_lo);
    cudaGetSymbolAddress((void**)&p_wp_hi, g_wp_hi);
    cudaGetSymbolAddress((void**)&p_wp_lo, g_wp_lo);
    cudaGetSymbolAddress((void**)&p_w1_hi, g_w1_hi);
    cudaGetSymbolAddress((void**)&p_w1_lo, g_w1_lo);
    cudaGetSymbolAddress((void**)&p_w2_hi, g_w2_hi);
    cudaGetSymbolAddress((void**)&p_w2_lo, g_w2_lo);
    cudaGetSymbolAddress((void**)&p_wa_hi, g_wa_hi);
    cudaGetSymbolAddress((void**)&p_wa_lo, g_wa_lo);

    dim3 tb(32, 8);

    // ---- pillar stage (k_pgemm at launch index 3 for ncu capture) ----
    k_zero<<<1024, 256>>>(Wa);                          // 0
    k_cell<<<TOTPTS / 256, 256>>>(x);                   // 1
    k_pointmlp<<<TOTPTS / 256, 256>>>(x, W1, W2, W3);   // 2
    k_pgemm<<<dim3(DD / 128, TOTPTS / 128), 256, SMEM_GEMM>>>(p_wa_hi, p_wa_lo);  // 3

    // weight transposes (64-wide K tiles, vectorized bf162 stores)
    k_wT<<<dim3(2304 / 32, 768 / 64, DEPTH), tb>>>(qkv_w, p_wq_hi, p_wq_lo, 768, 2304);
    k_wT<<<dim3(768 / 32, 768 / 64, DEPTH), tb>>>(proj_w, p_wp_hi, p_wp_lo, 768, 768);
    k_wT<<<dim3(3072 / 32, 768 / 64, DEPTH), tb>>>(fc1_w, p_w1_hi, p_w1_lo, 768, 3072);
    k_wT<<<dim3(768 / 32, 3072 / 64, DEPTH), tb>>>(fc2_w, p_w2_hi, p_w2_lo, 3072, 768);

    k_tokens<<<(BT * DD + 255) / 256, 256>>>(cls, pos, bn_g, bn_b, bn_m, bn_v);

    // ---- transformer ----
    const int mtiles64 = (BT + 63) / 64;    // 51
    const int lngrid = (BT + 7) / 8;        // 404
    for (int l = 0; l < DEPTH; l++) {
        k_ln<<<lngrid, 256>>>(p_tokens, ln1_g + (size_t)l * DD, ln1_b + (size_t)l * DD,
                              p_y_hi, p_y_lo);
        k_tgemm64<0><<<dim3(3 * DD / 64, mtiles64, 1), 128, SMEM_GEMM64>>>(
            p_y_hi, p_y_lo, p_wq_hi + (size_t)l * 3 * DD * DD, p_wq_lo + (size_t)l * 3 * DD * DD,
            nullptr, p_qkv, nullptr, nullptr, BT, 3 * DD, DD);
        k_attn<<<BB * HEADS, 256, SMEM_ATTN>>>();
        k_tgemm64<1><<<dim3(DD / 64, mtiles64, 2), 128, SMEM_GEMM64>>>(
            p_o_hi, p_o_lo, p_wp_hi + (size_t)l * DD * DD, p_wp_lo + (size_t)l * DD * DD,
            proj_b + (size_t)l * DD, p_tokens, nullptr, nullptr, BT, DD, DD);
        k_ln<<<lngrid, 256>>>(p_tokens, ln2_g + (size_t)l * DD, ln2_b + (size_t)l * DD,
                              p_y_hi, p_y_lo);
        k_tgemm64<2><<<dim3(MLPH / 64, mtiles64, 1), 128, SMEM_GEMM64>>>(
            p_y_hi, p_y_lo, p_w1_hi + (size_t)l * MLPH * DD, p_w1_lo + (size_t)l * MLPH * DD,
            fc1_b + (size_t)l * MLPH, nullptr, p_m_hi, p_m_lo, BT, MLPH, DD);
        k_tgemm64<1><<<dim3(DD / 64, mtiles64, 3), 128, SMEM_GEMM64>>>(
            p_m_hi, p_m_lo, p_w2_hi + (size_t)l * DD * MLPH, p_w2_lo + (size_t)l * DD * MLPH,
            fc2_b + (size_t)l * DD, p_tokens, nullptr, nullptr, BT, DD, MLPH);
    }

    // ---- head ----
    k_head<<<BB, 256>>>(norm_g, norm_b, head_w, head_b, out);
}